// round 1
// baseline (speedup 1.0000x reference)
#include <cuda_runtime.h>
#include <cuda_bf16.h>
#include <math.h>

// Problem constants
#define BATCH 2
#define SEQ 2048
#define DMODEL 1024
#define NHEADS 16
#define HDIM 64
#define MROWS (BATCH*SEQ)              // 4096
#define OUTN  (BATCH*SEQ*DMODEL)       // 4194304
#define KVN   (BATCH*NHEADS*SEQ*HDIM)  // 4194304

// ---------------- scratch (device globals; no allocations allowed) ----------
__device__ float g_qtmp[OUTN];
__device__ float g_ktmp[OUTN];
__device__ float g_vtmp[OUTN];
__device__ float g_q[KVN];     // q in [B,H,S,hd] after rope
__device__ float g_kfb[KVN];   // fallback k if out buffer has no kv region
__device__ float g_vfb[KVN];
__device__ float g_attn[OUTN]; // attention output in [B,S,D]

// ---------------- GEMM: C[M,N] = A[M,K] * B[N,K]^T  (both K-major) ----------
#define GBM 128
#define GBN 128
#define GBK 16

__global__ void __launch_bounds__(256) gemm_nt(const float* __restrict__ A,
                                               const float* __restrict__ B,
                                               float* __restrict__ C,
                                               int M, int N, int K)
{
    __shared__ float As[GBK][GBM];
    __shared__ float Bs[GBK][GBN];

    const int tid = threadIdx.x;
    const int tx = tid & 15;        // 0..15  -> N microtile
    const int ty = tid >> 4;        // 0..15  -> M microtile
    const int bm = blockIdx.y * GBM;
    const int bn = blockIdx.x * GBN;

    const float* Ab = A + (size_t)bm * K;
    const float* Bb = B + (size_t)bn * K;

    float acc[8][8];
#pragma unroll
    for (int i = 0; i < 8; i++)
#pragma unroll
        for (int j = 0; j < 8; j++) acc[i][j] = 0.f;

    for (int k0 = 0; k0 < K; k0 += GBK) {
        // load 128x16 tiles of A and B (K-major) into transposed smem
#pragma unroll
        for (int it = 0; it < 2; it++) {
            int idx = tid + it * 256;        // 0..511 (512 float4 per tile)
            int row = idx >> 2;              // 0..127
            int kq  = (idx & 3) << 2;        // 0,4,8,12
            float4 a = *(const float4*)(Ab + (size_t)row * K + k0 + kq);
            As[kq + 0][row] = a.x; As[kq + 1][row] = a.y;
            As[kq + 2][row] = a.z; As[kq + 3][row] = a.w;
            float4 b = *(const float4*)(Bb + (size_t)row * K + k0 + kq);
            Bs[kq + 0][row] = b.x; Bs[kq + 1][row] = b.y;
            Bs[kq + 2][row] = b.z; Bs[kq + 3][row] = b.w;
        }
        __syncthreads();

#pragma unroll
        for (int k = 0; k < GBK; k++) {
            float a[8], b[8];
            *(float4*)(a)     = *(const float4*)&As[k][ty * 8];
            *(float4*)(a + 4) = *(const float4*)&As[k][ty * 8 + 4];
            *(float4*)(b)     = *(const float4*)&Bs[k][tx * 8];
            *(float4*)(b + 4) = *(const float4*)&Bs[k][tx * 8 + 4];
#pragma unroll
            for (int i = 0; i < 8; i++)
#pragma unroll
                for (int j = 0; j < 8; j++) acc[i][j] = fmaf(a[i], b[j], acc[i][j]);
        }
        __syncthreads();
    }

#pragma unroll
    for (int i = 0; i < 8; i++) {
        float* crow = C + (size_t)(bm + ty * 8 + i) * N + bn + tx * 8;
#pragma unroll
        for (int j = 0; j < 8; j += 4) {
            float4 v = make_float4(acc[i][j], acc[i][j+1], acc[i][j+2], acc[i][j+3]);
            *(float4*)(crow + j) = v;
        }
    }
}

// ---------------- RoPE + transpose to [B,H,S,hd]; also copies V -------------
// one thread per rotation pair (32 pairs per head-vector)
__global__ void rope_kernel(const float* __restrict__ qtmp,
                            const float* __restrict__ ktmp,
                            const float* __restrict__ vtmp,
                            float* __restrict__ q,
                            float* __restrict__ k,
                            float* __restrict__ v)
{
    int i = blockIdx.x * blockDim.x + threadIdx.x;
    const int NPAIR = BATCH * SEQ * NHEADS * (HDIM / 2);  // 2097152
    if (i >= NPAIR) return;

    int p = i & 31;
    int h = (i >> 5) & (NHEADS - 1);
    int s = (i >> 9) & (SEQ - 1);
    int b = i >> 20;

    size_t src = ((size_t)(b * SEQ + s) * DMODEL + h * HDIM) + 2 * p;
    size_t dst = (((size_t)(b * NHEADS + h) * SEQ + s) * HDIM) + 2 * p;

    // inv_freq = 10000^(-2p/64) = exp(-p * ln(1e4)/32), done in double for accuracy
    float invf = (float)exp(-(double)p * 0.2878231366242557);
    float ang = (float)s * invf;
    float c, sn;
    sincosf(ang, &sn, &c);

    float q1 = qtmp[src], q2 = qtmp[src + 1];
    q[dst]     = q1 * c - q2 * sn;
    q[dst + 1] = q1 * sn + q2 * c;

    float k1 = ktmp[src], k2 = ktmp[src + 1];
    k[dst]     = k1 * c - k2 * sn;
    k[dst + 1] = k1 * sn + k2 * c;

    v[dst]     = vtmp[src];
    v[dst + 1] = vtmp[src + 1];
}

// ---------------- causal flash attention (fp32) ------------------------------
// Q,K,V in [B,H,S,hd]; O in [B,S,D]. Tile: 64 queries x 32 keys. 256 threads.
#define FBQ 64
#define FBK 32

__global__ void __launch_bounds__(256) flash_kernel(const float* __restrict__ Q,
                                                    const float* __restrict__ K,
                                                    const float* __restrict__ V,
                                                    float* __restrict__ O)
{
    __shared__ float sQ[FBQ][HDIM + 1];
    __shared__ float sKt[HDIM][FBK + 1];   // [dim][key]
    __shared__ float sV[FBK][HDIM];        // [key][dim]
    __shared__ float sP[FBQ][FBK + 1];
    __shared__ float sM[FBQ], sL[FBQ], sA[FBQ];

    const int qt = blockIdx.x;
    const int h  = blockIdx.y;
    const int b  = blockIdx.z;
    const int tid = threadIdx.x;
    const int tx = tid & 15;   // cols
    const int ty = tid >> 4;   // rows
    const int q0 = qt * FBQ;

    const float* qb = Q + ((size_t)(b * NHEADS + h) * SEQ + q0) * HDIM;
    const float* kb = K + (size_t)(b * NHEADS + h) * SEQ * HDIM;
    const float* vb = V + (size_t)(b * NHEADS + h) * SEQ * HDIM;

    // load Q tile (coalesced)
#pragma unroll
    for (int it = 0; it < 16; it++) {
        int idx = tid + it * 256;
        int r = idx >> 6, c = idx & 63;
        sQ[r][c] = qb[(size_t)r * HDIM + c];
    }
    if (tid < FBQ) { sM[tid] = -1e30f; sL[tid] = 0.f; }

    float acc[4][4];
#pragma unroll
    for (int i = 0; i < 4; i++)
#pragma unroll
        for (int j = 0; j < 4; j++) acc[i][j] = 0.f;

    const int nkt = 2 * qt + 2;   // key tiles covering keys 0..q0+63
    for (int kt = 0; kt < nkt; kt++) {
        __syncthreads();
        // load K (transposed) and V tiles
#pragma unroll
        for (int it = 0; it < 8; it++) {
            int idx = tid + it * 256;         // 0..2047
            int kr = idx >> 6, c = idx & 63;  // key-in-tile, dim
            size_t g = (size_t)(kt * FBK + kr) * HDIM + c;
            sKt[c][kr] = kb[g];
            sV[kr][c]  = vb[g];
        }
        __syncthreads();

        // scores: 4 rows x 2 cols per thread
        float s00=0,s01=0,s10=0,s11=0,s20=0,s21=0,s30=0,s31=0;
#pragma unroll
        for (int k = 0; k < HDIM; k++) {
            float a0 = sQ[ty*4+0][k], a1 = sQ[ty*4+1][k];
            float a2 = sQ[ty*4+2][k], a3 = sQ[ty*4+3][k];
            float b0 = sKt[k][tx*2+0], b1 = sKt[k][tx*2+1];
            s00 = fmaf(a0,b0,s00); s01 = fmaf(a0,b1,s01);
            s10 = fmaf(a1,b0,s10); s11 = fmaf(a1,b1,s11);
            s20 = fmaf(a2,b0,s20); s21 = fmaf(a2,b1,s21);
            s30 = fmaf(a3,b0,s30); s31 = fmaf(a3,b1,s31);
        }
        const float sc = 0.125f;  // 1/sqrt(64)
        int kg0 = kt * FBK + tx * 2, kg1 = kg0 + 1;
        {
            int qg = q0 + ty * 4;
            sP[ty*4+0][tx*2+0] = (kg0 > qg+0) ? -1e30f : s00 * sc;
            sP[ty*4+0][tx*2+1] = (kg1 > qg+0) ? -1e30f : s01 * sc;
            sP[ty*4+1][tx*2+0] = (kg0 > qg+1) ? -1e30f : s10 * sc;
            sP[ty*4+1][tx*2+1] = (kg1 > qg+1) ? -1e30f : s11 * sc;
            sP[ty*4+2][tx*2+0] = (kg0 > qg+2) ? -1e30f : s20 * sc;
            sP[ty*4+2][tx*2+1] = (kg1 > qg+2) ? -1e30f : s21 * sc;
            sP[ty*4+3][tx*2+0] = (kg0 > qg+3) ? -1e30f : s30 * sc;
            sP[ty*4+3][tx*2+1] = (kg1 > qg+3) ? -1e30f : s31 * sc;
        }
        __syncthreads();

        // online softmax row pass (64 threads, one per row)
        if (tid < FBQ) {
            float m = sM[tid];
            float rmax = m;
#pragma unroll
            for (int j = 0; j < FBK; j++) rmax = fmaxf(rmax, sP[tid][j]);
            float alpha = __expf(m - rmax);
            float sum = 0.f;
#pragma unroll
            for (int j = 0; j < FBK; j++) {
                float p = __expf(sP[tid][j] - rmax);
                sP[tid][j] = p;
                sum += p;
            }
            sM[tid] = rmax;
            sL[tid] = sL[tid] * alpha + sum;
            sA[tid] = alpha;
        }
        __syncthreads();

        // rescale accumulators + P@V
#pragma unroll
        for (int i = 0; i < 4; i++) {
            float a = sA[ty*4+i];
            acc[i][0]*=a; acc[i][1]*=a; acc[i][2]*=a; acc[i][3]*=a;
        }
#pragma unroll
        for (int k = 0; k < FBK; k++) {
            float p0 = sP[ty*4+0][k], p1 = sP[ty*4+1][k];
            float p2 = sP[ty*4+2][k], p3 = sP[ty*4+3][k];
            float4 v4 = *(const float4*)&sV[k][tx*4];
            acc[0][0]=fmaf(p0,v4.x,acc[0][0]); acc[0][1]=fmaf(p0,v4.y,acc[0][1]);
            acc[0][2]=fmaf(p0,v4.z,acc[0][2]); acc[0][3]=fmaf(p0,v4.w,acc[0][3]);
            acc[1][0]=fmaf(p1,v4.x,acc[1][0]); acc[1][1]=fmaf(p1,v4.y,acc[1][1]);
            acc[1][2]=fmaf(p1,v4.z,acc[1][2]); acc[1][3]=fmaf(p1,v4.w,acc[1][3]);
            acc[2][0]=fmaf(p2,v4.x,acc[2][0]); acc[2][1]=fmaf(p2,v4.y,acc[2][1]);
            acc[2][2]=fmaf(p2,v4.z,acc[2][2]); acc[2][3]=fmaf(p2,v4.w,acc[2][3]);
            acc[3][0]=fmaf(p3,v4.x,acc[3][0]); acc[3][1]=fmaf(p3,v4.y,acc[3][1]);
            acc[3][2]=fmaf(p3,v4.z,acc[3][2]); acc[3][3]=fmaf(p3,v4.w,acc[3][3]);
        }
    }
    __syncthreads();

    // finalize: divide by l, write [B,S,D]
#pragma unroll
    for (int i = 0; i < 4; i++) {
        float inv = 1.f / sL[ty*4+i];
        float* orow = O + (size_t)(b * SEQ + q0 + ty*4 + i) * DMODEL + h * HDIM + tx * 4;
        float4 o = make_float4(acc[i][0]*inv, acc[i][1]*inv, acc[i][2]*inv, acc[i][3]*inv);
        *(float4*)orow = o;
    }
}

// ---------------- launcher ---------------------------------------------------
extern "C" void kernel_launch(void* const* d_in, const int* in_sizes, int n_in,
                              void* d_out, int out_size)
{
    const float* x  = (const float*)d_in[0];
    // d_in[1] = mask (causal, known analytically; ignored)
    const float* Wq = (const float*)d_in[2];
    const float* Wk = (const float*)d_in[3];
    const float* Wv = (const float*)d_in[4];
    const float* Wo = (const float*)d_in[5];
    float* out = (float*)d_out;

    float *qtmp, *ktmp, *vtmp, *q, *kfb, *vfb, *attn;
    cudaGetSymbolAddress((void**)&qtmp, g_qtmp);
    cudaGetSymbolAddress((void**)&ktmp, g_ktmp);
    cudaGetSymbolAddress((void**)&vtmp, g_vtmp);
    cudaGetSymbolAddress((void**)&q,    g_q);
    cudaGetSymbolAddress((void**)&kfb,  g_kfb);
    cudaGetSymbolAddress((void**)&vfb,  g_vfb);
    cudaGetSymbolAddress((void**)&attn, g_attn);

    // output layout: [out (B,S,D)] [k (B,H,S,hd)] [v (B,H,S,hd)]
    float* kdst;
    float* vdst;
    if (out_size >= OUTN + 2 * KVN) {
        kdst = out + OUTN;
        vdst = out + OUTN + KVN;
    } else {
        kdst = kfb;
        vdst = vfb;
    }

    dim3 gemm_grid(DMODEL / GBN, MROWS / GBM);  // (8, 32)
    gemm_nt<<<gemm_grid, 256>>>(x, Wq, qtmp, MROWS, DMODEL, DMODEL);
    gemm_nt<<<gemm_grid, 256>>>(x, Wk, ktmp, MROWS, DMODEL, DMODEL);
    gemm_nt<<<gemm_grid, 256>>>(x, Wv, vtmp, MROWS, DMODEL, DMODEL);

    const int NPAIR = BATCH * SEQ * NHEADS * (HDIM / 2);
    rope_kernel<<<(NPAIR + 255) / 256, 256>>>(qtmp, ktmp, vtmp, q, kdst, vdst);

    dim3 fgrid(SEQ / FBQ, NHEADS, BATCH);       // (32, 16, 2)
    flash_kernel<<<fgrid, 256>>>(q, kdst, vdst, attn);

    gemm_nt<<<gemm_grid, 256>>>(attn, Wo, out, MROWS, DMODEL, DMODEL);
}

// round 3
// speedup vs baseline: 2.8132x; 2.8132x over previous
#include <cuda_runtime.h>
#include <cuda_bf16.h>
#include <math.h>
#include <stdint.h>

// Problem constants
#define BATCH 2
#define SEQ 2048
#define DMODEL 1024
#define NHEADS 16
#define HDIM 64
#define MROWS (BATCH*SEQ)              // 4096
#define OUTN  (BATCH*SEQ*DMODEL)       // 4194304
#define KVN   (BATCH*NHEADS*SEQ*HDIM)  // 4194304
#define WN    (DMODEL*DMODEL)          // 1048576

// ---------------- scratch (device globals; no allocations allowed) ----------
__device__ float g_qtmp[OUTN];
__device__ float g_ktmp[OUTN];
__device__ float g_vtmp[OUTN];
__device__ float g_q[KVN];
__device__ float g_kfb[KVN];
__device__ float g_vfb[KVN];
__device__ float g_attn[OUTN];
// bf16 split buffers
__device__ __nv_bfloat16 g_xh[OUTN];
__device__ __nv_bfloat16 g_xl[OUTN];
__device__ __nv_bfloat16 g_wqh[WN], g_wql[WN];
__device__ __nv_bfloat16 g_wkh[WN], g_wkl[WN];
__device__ __nv_bfloat16 g_wvh[WN], g_wvl[WN];
__device__ __nv_bfloat16 g_woh[WN], g_wol[WN];

// ====================== helpers ==============================================
__device__ __forceinline__ uint32_t smem_to_u32(const void* p) {
    uint32_t a;
    asm("{ .reg .u64 t; cvta.to.shared.u64 t, %1; cvt.u32.u64 %0, t; }"
        : "=r"(a) : "l"(p));
    return a;
}

__device__ __forceinline__ void cp16(uint32_t saddr, const void* g) {
    asm volatile("cp.async.cg.shared.global [%0], [%1], 16;"
                 :: "r"(saddr), "l"(g) : "memory");
}

#define LDSM4(r0, r1, r2, r3, addr) \
    asm volatile("ldmatrix.sync.aligned.m8n8.x4.shared.b16 {%0,%1,%2,%3}, [%4];" \
                 : "=r"(r0), "=r"(r1), "=r"(r2), "=r"(r3) : "r"(addr))

#define MMA16816(d, a0, a1, a2, a3, b0, b1) \
    asm volatile("mma.sync.aligned.m16n8k16.row.col.f32.bf16.bf16.f32 " \
                 "{%0,%1,%2,%3}, {%4,%5,%6,%7}, {%8,%9}, {%0,%1,%2,%3};" \
                 : "+f"((d)[0]), "+f"((d)[1]), "+f"((d)[2]), "+f"((d)[3]) \
                 : "r"(a0), "r"(a1), "r"(a2), "r"(a3), "r"(b0), "r"(b1))

// ====================== bf16 split conversion ================================
__global__ void split_kernel(const float4* __restrict__ src,
                             __nv_bfloat162* __restrict__ hi,
                             __nv_bfloat162* __restrict__ lo, int n4)
{
    int i = blockIdx.x * blockDim.x + threadIdx.x;
    if (i >= n4) return;
    float4 v = src[i];
    __nv_bfloat16 h0 = __float2bfloat16(v.x);
    __nv_bfloat16 h1 = __float2bfloat16(v.y);
    __nv_bfloat16 h2 = __float2bfloat16(v.z);
    __nv_bfloat16 h3 = __float2bfloat16(v.w);
    float r0 = v.x - __bfloat162float(h0);
    float r1 = v.y - __bfloat162float(h1);
    float r2 = v.z - __bfloat162float(h2);
    float r3 = v.w - __bfloat162float(h3);
    hi[2*i]   = __halves2bfloat162(h0, h1);
    hi[2*i+1] = __halves2bfloat162(h2, h3);
    lo[2*i]   = __halves2bfloat162(__float2bfloat16(r0), __float2bfloat16(r1));
    lo[2*i+1] = __halves2bfloat162(__float2bfloat16(r2), __float2bfloat16(r3));
}

// ====================== mma.sync split-bf16 GEMM ==============================
// C[4096,1024] = A[4096,1024] * B[1024,1024]^T via AhBh + AhBl + AlBh.
// Block tile 128x128, K-chunk 64, cp.async double-buffered, 8 warps.
#define TB 16384                 // one 128x64 bf16 tile (128B rows)
#define STAGE (4*TB)             // Ah, Al, Bh, Bl
#define GEMM_SMEM (2*STAGE)      // 131072
#define NCK 16                   // 1024/64

__device__ __forceinline__ void stage_load(uint32_t sb,
    const uint4* __restrict__ Ah, const uint4* __restrict__ Al,
    const uint4* __restrict__ Bh, const uint4* __restrict__ Bl,
    int m0, int n0, int c, int tid)
{
    const int q = tid & 7;
    const int r0 = tid >> 3;   // 0..31
#pragma unroll
    for (int it = 0; it < 4; it++) {
        int row = r0 + it * 32;
        uint32_t off = row * 128 + q * 16;
        off ^= (off >> 3) & 0x70;
        size_t ga = (size_t)(m0 + row) * 128 + c * 8 + q;
        size_t gb = (size_t)(n0 + row) * 128 + c * 8 + q;
        cp16(sb + off,          Ah + ga);
        cp16(sb + TB + off,     Al + ga);
        cp16(sb + 2*TB + off,   Bh + gb);
        cp16(sb + 3*TB + off,   Bl + gb);
    }
}

__global__ void __launch_bounds__(256) mma_gemm(const __nv_bfloat16* __restrict__ Ah_,
                                                const __nv_bfloat16* __restrict__ Al_,
                                                const __nv_bfloat16* __restrict__ Bh_,
                                                const __nv_bfloat16* __restrict__ Bl_,
                                                float* __restrict__ C)
{
    extern __shared__ char smem[];
    const uint32_t sbase = smem_to_u32(smem);
    const int tid = threadIdx.x;
    const int wid = tid >> 5;
    const int lane = tid & 31;
    const int m0 = blockIdx.y * 128;
    const int n0 = blockIdx.x * 128;
    const int wm = (wid & 1) * 64;     // warp row offset
    const int wn = (wid >> 1) * 32;    // warp col offset

    // ldmatrix lane addressing
    const int t  = lane >> 3;
    const int li = lane & 7;
    const int arow  = (t & 1) * 8 + li;         // A tiles: (m0,k0),(m8,k0),(m0,k8),(m8,k8)
    const int acolb = (t >> 1) * 16;
    const int brow  = ((t >> 1) & 1) * 8 + li;  // B tiles: (n0,k0),(n0,k8),(n8,k0),(n8,k8)
    const int bcolb = (t & 1) * 16;

    const uint4* A4h = (const uint4*)Ah_;
    const uint4* A4l = (const uint4*)Al_;
    const uint4* B4h = (const uint4*)Bh_;
    const uint4* B4l = (const uint4*)Bl_;

    float acc[4][4][4];
#pragma unroll
    for (int i = 0; i < 4; i++)
#pragma unroll
        for (int j = 0; j < 4; j++)
#pragma unroll
            for (int r = 0; r < 4; r++) acc[i][j][r] = 0.f;

    stage_load(sbase, A4h, A4l, B4h, B4l, m0, n0, 0, tid);
    asm volatile("cp.async.commit_group;" ::: "memory");

    for (int c = 0; c < NCK; c++) {
        __syncthreads();  // all warps done reading the stage we are about to overwrite
        if (c + 1 < NCK) {
            stage_load(sbase + (uint32_t)((c + 1) & 1) * STAGE,
                       A4h, A4l, B4h, B4l, m0, n0, c + 1, tid);
            asm volatile("cp.async.commit_group;" ::: "memory");
            asm volatile("cp.async.wait_group 1;" ::: "memory");
        } else {
            asm volatile("cp.async.wait_group 0;" ::: "memory");
        }
        __syncthreads();

        const uint32_t sb  = sbase + (uint32_t)(c & 1) * STAGE;
        const uint32_t sAh = sb;
        const uint32_t sAl = sb + TB;
        const uint32_t sBh = sb + 2*TB;
        const uint32_t sBl = sb + 3*TB;

#pragma unroll
        for (int kk = 0; kk < 4; kk++) {
            uint32_t bh[4][2], bl[4][2];
#pragma unroll
            for (int nf2 = 0; nf2 < 2; nf2++) {
                uint32_t off = (uint32_t)(wn + nf2 * 16 + brow) * 128 + kk * 32 + bcolb;
                off ^= (off >> 3) & 0x70;
                LDSM4(bh[nf2*2+0][0], bh[nf2*2+0][1], bh[nf2*2+1][0], bh[nf2*2+1][1], sBh + off);
                LDSM4(bl[nf2*2+0][0], bl[nf2*2+0][1], bl[nf2*2+1][0], bl[nf2*2+1][1], sBl + off);
            }
#pragma unroll
            for (int mf = 0; mf < 4; mf++) {
                uint32_t off = (uint32_t)(wm + mf * 16 + arow) * 128 + kk * 32 + acolb;
                off ^= (off >> 3) & 0x70;
                uint32_t ah0, ah1, ah2, ah3, al0, al1, al2, al3;
                LDSM4(ah0, ah1, ah2, ah3, sAh + off);
                LDSM4(al0, al1, al2, al3, sAl + off);
#pragma unroll
                for (int nf = 0; nf < 4; nf++) {
                    MMA16816(acc[mf][nf], ah0, ah1, ah2, ah3, bh[nf][0], bh[nf][1]);
                    MMA16816(acc[mf][nf], ah0, ah1, ah2, ah3, bl[nf][0], bl[nf][1]);
                    MMA16816(acc[mf][nf], al0, al1, al2, al3, bh[nf][0], bh[nf][1]);
                }
            }
        }
    }

    // epilogue
    const int g  = lane >> 2;
    const int tq = lane & 3;
#pragma unroll
    for (int mf = 0; mf < 4; mf++) {
#pragma unroll
        for (int nf = 0; nf < 4; nf++) {
            int rr = m0 + wm + mf * 16 + g;
            int cc = n0 + wn + nf * 8 + tq * 2;
            *(float2*)&C[(size_t)rr * DMODEL + cc]       = make_float2(acc[mf][nf][0], acc[mf][nf][1]);
            *(float2*)&C[(size_t)(rr + 8) * DMODEL + cc] = make_float2(acc[mf][nf][2], acc[mf][nf][3]);
        }
    }
}

// ---------------- RoPE + transpose to [B,H,S,hd]; also copies V -------------
struct RopeTab { float hi[32]; float lo[32]; };

__global__ void rope_kernel(const float* __restrict__ qtmp,
                            const float* __restrict__ ktmp,
                            const float* __restrict__ vtmp,
                            float* __restrict__ q,
                            float* __restrict__ k,
                            float* __restrict__ v,
                            RopeTab tab)
{
    int i = blockIdx.x * blockDim.x + threadIdx.x;
    const int NPAIR = BATCH * SEQ * NHEADS * (HDIM / 2);
    if (i >= NPAIR) return;

    int p = i & 31;
    int h = (i >> 5) & (NHEADS - 1);
    int s = (i >> 9) & (SEQ - 1);
    int b = i >> 20;

    size_t src = ((size_t)(b * SEQ + s) * DMODEL + h * HDIM) + 2 * p;
    size_t dst = (((size_t)(b * NHEADS + h) * SEQ + s) * HDIM) + 2 * p;

    float fs = (float)s;
    float ang = fmaf(fs, tab.lo[p], fs * tab.hi[p]);
    float c, sn;
    sincosf(ang, &sn, &c);

    float q1 = qtmp[src], q2 = qtmp[src + 1];
    q[dst]     = q1 * c - q2 * sn;
    q[dst + 1] = q1 * sn + q2 * c;

    float k1 = ktmp[src], k2 = ktmp[src + 1];
    k[dst]     = k1 * c - k2 * sn;
    k[dst + 1] = k1 * sn + k2 * c;

    v[dst]     = vtmp[src];
    v[dst + 1] = vtmp[src + 1];
}

// ---------------- causal flash attention (fp32) ------------------------------
#define FBQ 64
#define FBK 32

__global__ void __launch_bounds__(256) flash_kernel(const float* __restrict__ Q,
                                                    const float* __restrict__ K,
                                                    const float* __restrict__ V,
                                                    float* __restrict__ O)
{
    __shared__ float sQ[FBQ][HDIM + 1];
    __shared__ float sKt[HDIM][FBK + 1];
    __shared__ float sV[FBK][HDIM];
    __shared__ float sP[FBQ][FBK + 1];

    const int qt = gridDim.x - 1 - blockIdx.x;  // heavy blocks first
    const int h  = blockIdx.y;
    const int b  = blockIdx.z;
    const int tid = threadIdx.x;
    const int tx = tid & 15;
    const int ty = tid >> 4;
    const int q0 = qt * FBQ;

    const float* qb = Q + ((size_t)(b * NHEADS + h) * SEQ + q0) * HDIM;
    const float* kb = K + (size_t)(b * NHEADS + h) * SEQ * HDIM;
    const float* vb = V + (size_t)(b * NHEADS + h) * SEQ * HDIM;

#pragma unroll
    for (int it = 0; it < 16; it++) {
        int idx = tid + it * 256;
        int r = idx >> 6, c = idx & 63;
        sQ[r][c] = qb[(size_t)r * HDIM + c];
    }

    float acc[4][4];
#pragma unroll
    for (int i = 0; i < 4; i++)
#pragma unroll
        for (int j = 0; j < 4; j++) acc[i][j] = 0.f;

    float m_i[4], l_i[4], a_i[4];
#pragma unroll
    for (int i = 0; i < 4; i++) { m_i[i] = -1e30f; l_i[i] = 0.f; }

    const int nkt = 2 * qt + 2;
    for (int kt = 0; kt < nkt; kt++) {
        __syncthreads();
#pragma unroll
        for (int it = 0; it < 8; it++) {
            int idx = tid + it * 256;
            int kr = idx >> 6, c = idx & 63;
            size_t g = (size_t)(kt * FBK + kr) * HDIM + c;
            sKt[c][kr] = kb[g];
            sV[kr][c]  = vb[g];
        }
        __syncthreads();

        float s00=0,s01=0,s10=0,s11=0,s20=0,s21=0,s30=0,s31=0;
#pragma unroll
        for (int k = 0; k < HDIM; k++) {
            float a0 = sQ[ty*4+0][k], a1 = sQ[ty*4+1][k];
            float a2 = sQ[ty*4+2][k], a3 = sQ[ty*4+3][k];
            float b0 = sKt[k][tx*2+0], b1 = sKt[k][tx*2+1];
            s00 = fmaf(a0,b0,s00); s01 = fmaf(a0,b1,s01);
            s10 = fmaf(a1,b0,s10); s11 = fmaf(a1,b1,s11);
            s20 = fmaf(a2,b0,s20); s21 = fmaf(a2,b1,s21);
            s30 = fmaf(a3,b0,s30); s31 = fmaf(a3,b1,s31);
        }
        const float sc = 0.125f;
        int kg0 = kt * FBK + tx * 2, kg1 = kg0 + 1;
        float sreg[4][2];
        {
            int qg = q0 + ty * 4;
            sreg[0][0] = (kg0 > qg+0) ? -1e30f : s00 * sc;
            sreg[0][1] = (kg1 > qg+0) ? -1e30f : s01 * sc;
            sreg[1][0] = (kg0 > qg+1) ? -1e30f : s10 * sc;
            sreg[1][1] = (kg1 > qg+1) ? -1e30f : s11 * sc;
            sreg[2][0] = (kg0 > qg+2) ? -1e30f : s20 * sc;
            sreg[2][1] = (kg1 > qg+2) ? -1e30f : s21 * sc;
            sreg[3][0] = (kg0 > qg+3) ? -1e30f : s30 * sc;
            sreg[3][1] = (kg1 > qg+3) ? -1e30f : s31 * sc;
        }

        // distributed online softmax: 16-lane row groups
#pragma unroll
        for (int i = 0; i < 4; i++) {
            float mx = fmaxf(sreg[i][0], sreg[i][1]);
#pragma unroll
            for (int d = 1; d < 16; d <<= 1)
                mx = fmaxf(mx, __shfl_xor_sync(0xffffffffu, mx, d));
            float mnew = fmaxf(m_i[i], mx);
            float p0 = __expf(sreg[i][0] - mnew);
            float p1 = __expf(sreg[i][1] - mnew);
            float sum = p0 + p1;
#pragma unroll
            for (int d = 1; d < 16; d <<= 1)
                sum += __shfl_xor_sync(0xffffffffu, sum, d);
            float alpha = __expf(m_i[i] - mnew);
            l_i[i] = l_i[i] * alpha + sum;
            m_i[i] = mnew;
            a_i[i] = alpha;
            sP[ty*4+i][tx*2+0] = p0;
            sP[ty*4+i][tx*2+1] = p1;
        }
        __syncthreads();

#pragma unroll
        for (int i = 0; i < 4; i++) {
            float a = a_i[i];
            acc[i][0]*=a; acc[i][1]*=a; acc[i][2]*=a; acc[i][3]*=a;
        }
#pragma unroll
        for (int k = 0; k < FBK; k++) {
            float p0 = sP[ty*4+0][k], p1 = sP[ty*4+1][k];
            float p2 = sP[ty*4+2][k], p3 = sP[ty*4+3][k];
            float4 v4 = *(const float4*)&sV[k][tx*4];
            acc[0][0]=fmaf(p0,v4.x,acc[0][0]); acc[0][1]=fmaf(p0,v4.y,acc[0][1]);
            acc[0][2]=fmaf(p0,v4.z,acc[0][2]); acc[0][3]=fmaf(p0,v4.w,acc[0][3]);
            acc[1][0]=fmaf(p1,v4.x,acc[1][0]); acc[1][1]=fmaf(p1,v4.y,acc[1][1]);
            acc[1][2]=fmaf(p1,v4.z,acc[1][2]); acc[1][3]=fmaf(p1,v4.w,acc[1][3]);
            acc[2][0]=fmaf(p2,v4.x,acc[2][0]); acc[2][1]=fmaf(p2,v4.y,acc[2][1]);
            acc[2][2]=fmaf(p2,v4.z,acc[2][2]); acc[2][3]=fmaf(p2,v4.w,acc[2][3]);
            acc[3][0]=fmaf(p3,v4.x,acc[3][0]); acc[3][1]=fmaf(p3,v4.y,acc[3][1]);
            acc[3][2]=fmaf(p3,v4.z,acc[3][2]); acc[3][3]=fmaf(p3,v4.w,acc[3][3]);
        }
    }

#pragma unroll
    for (int i = 0; i < 4; i++) {
        float inv = 1.f / l_i[i];
        float* orow = O + (size_t)(b * SEQ + q0 + ty*4 + i) * DMODEL + h * HDIM + tx * 4;
        float4 o = make_float4(acc[i][0]*inv, acc[i][1]*inv, acc[i][2]*inv, acc[i][3]*inv);
        *(float4*)orow = o;
    }
}

// ---------------- launcher ---------------------------------------------------
extern "C" void kernel_launch(void* const* d_in, const int* in_sizes, int n_in,
                              void* d_out, int out_size)
{
    const float* x  = (const float*)d_in[0];
    const float* Wq = (const float*)d_in[2];
    const float* Wk = (const float*)d_in[3];
    const float* Wv = (const float*)d_in[4];
    const float* Wo = (const float*)d_in[5];
    float* out = (float*)d_out;

    float *qtmp, *ktmp, *vtmp, *q, *kfb, *vfb, *attn;
    cudaGetSymbolAddress((void**)&qtmp, g_qtmp);
    cudaGetSymbolAddress((void**)&ktmp, g_ktmp);
    cudaGetSymbolAddress((void**)&vtmp, g_vtmp);
    cudaGetSymbolAddress((void**)&q,    g_q);
    cudaGetSymbolAddress((void**)&kfb,  g_kfb);
    cudaGetSymbolAddress((void**)&vfb,  g_vfb);
    cudaGetSymbolAddress((void**)&attn, g_attn);

    __nv_bfloat16 *xh, *xl, *wqh, *wql, *wkh, *wkl, *wvh, *wvl, *woh, *wol;
    cudaGetSymbolAddress((void**)&xh, g_xh);
    cudaGetSymbolAddress((void**)&xl, g_xl);
    cudaGetSymbolAddress((void**)&wqh, g_wqh);
    cudaGetSymbolAddress((void**)&wql, g_wql);
    cudaGetSymbolAddress((void**)&wkh, g_wkh);
    cudaGetSymbolAddress((void**)&wkl, g_wkl);
    cudaGetSymbolAddress((void**)&wvh, g_wvh);
    cudaGetSymbolAddress((void**)&wvl, g_wvl);
    cudaGetSymbolAddress((void**)&woh, g_woh);
    cudaGetSymbolAddress((void**)&wol, g_wol);

    float* kdst;
    float* vdst;
    if (out_size >= OUTN + 2 * KVN) {
        kdst = out + OUTN;
        vdst = out + OUTN + KVN;
    } else {
        kdst = kfb;
        vdst = vfb;
    }

    cudaFuncSetAttribute(mma_gemm, cudaFuncAttributeMaxDynamicSharedMemorySize, GEMM_SMEM);

    // host-exact RoPE inv_freq table (hi/lo split)
    RopeTab tab;
    for (int p = 0; p < 32; p++) {
        double invf = exp(-(double)p * (log(10000.0) / 32.0));
        float hi = (float)invf;
        tab.hi[p] = hi;
        tab.lo[p] = (float)(invf - (double)hi);
    }

    // bf16 splits
    split_kernel<<<OUTN/4/256, 256>>>((const float4*)x, (__nv_bfloat162*)xh, (__nv_bfloat162*)xl, OUTN/4);
    split_kernel<<<WN/4/256, 256>>>((const float4*)Wq, (__nv_bfloat162*)wqh, (__nv_bfloat162*)wql, WN/4);
    split_kernel<<<WN/4/256, 256>>>((const float4*)Wk, (__nv_bfloat162*)wkh, (__nv_bfloat162*)wkl, WN/4);
    split_kernel<<<WN/4/256, 256>>>((const float4*)Wv, (__nv_bfloat162*)wvh, (__nv_bfloat162*)wvl, WN/4);
    split_kernel<<<WN/4/256, 256>>>((const float4*)Wo, (__nv_bfloat162*)woh, (__nv_bfloat162*)wol, WN/4);

    // projections on tensor cores (mma.sync)
    dim3 ggrid(DMODEL / 128, MROWS / 128);   // (8, 32)
    mma_gemm<<<ggrid, 256, GEMM_SMEM>>>(xh, xl, wqh, wql, qtmp);
    mma_gemm<<<ggrid, 256, GEMM_SMEM>>>(xh, xl, wkh, wkl, ktmp);
    mma_gemm<<<ggrid, 256, GEMM_SMEM>>>(xh, xl, wvh, wvl, vtmp);

    const int NPAIR = BATCH * SEQ * NHEADS * (HDIM / 2);
    rope_kernel<<<(NPAIR + 255) / 256, 256>>>(qtmp, ktmp, vtmp, q, kdst, vdst, tab);

    dim3 fgrid(SEQ / FBQ, NHEADS, BATCH);
    flash_kernel<<<fgrid, 256>>>(q, kdst, vdst, attn);

    // output projection (reuse x split buffers for attn)
    split_kernel<<<OUTN/4/256, 256>>>((const float4*)attn, (__nv_bfloat162*)xh, (__nv_bfloat162*)xl, OUTN/4);
    mma_gemm<<<ggrid, 256, GEMM_SMEM>>>(xh, xl, woh, wol, out);
}

// round 4
// speedup vs baseline: 5.1554x; 1.8326x over previous
#include <cuda_runtime.h>
#include <cuda_bf16.h>
#include <math.h>
#include <stdint.h>

// Problem constants
#define BATCH 2
#define SEQ 2048
#define DMODEL 1024
#define NHEADS 16
#define HDIM 64
#define MROWS (BATCH*SEQ)              // 4096
#define OUTN  (BATCH*SEQ*DMODEL)       // 4194304
#define KVN   (BATCH*NHEADS*SEQ*HDIM)  // 4194304
#define WN    (DMODEL*DMODEL)          // 1048576

// ---------------- scratch (device globals; no allocations allowed) ----------
__device__ float g_qtmp[OUTN];
__device__ float g_ktmp[OUTN];
__device__ float g_vtmp[OUTN];
__device__ float g_kfb[KVN];
__device__ float g_vfb[KVN];
// bf16 split buffers (GEMM inputs)
__device__ __nv_bfloat16 g_xh[OUTN];
__device__ __nv_bfloat16 g_xl[OUTN];
__device__ __nv_bfloat16 g_wqh[WN], g_wql[WN];
__device__ __nv_bfloat16 g_wkh[WN], g_wkl[WN];
__device__ __nv_bfloat16 g_wvh[WN], g_wvl[WN];
__device__ __nv_bfloat16 g_woh[WN], g_wol[WN];
// bf16 split q/k/v in [B,H,S,hd] for tensor-core flash
__device__ __nv_bfloat16 g_qh[KVN], g_ql[KVN];
__device__ __nv_bfloat16 g_kh[KVN], g_kl[KVN];
__device__ __nv_bfloat16 g_vh[KVN], g_vl[KVN];

// ====================== helpers ==============================================
__device__ __forceinline__ uint32_t smem_to_u32(const void* p) {
    uint32_t a;
    asm("{ .reg .u64 t; cvta.to.shared.u64 t, %1; cvt.u32.u64 %0, t; }"
        : "=r"(a) : "l"(p));
    return a;
}

__device__ __forceinline__ void cp16(uint32_t saddr, const void* g) {
    asm volatile("cp.async.cg.shared.global [%0], [%1], 16;"
                 :: "r"(saddr), "l"(g) : "memory");
}

#define LDSM4(r0, r1, r2, r3, addr) \
    asm volatile("ldmatrix.sync.aligned.m8n8.x4.shared.b16 {%0,%1,%2,%3}, [%4];" \
                 : "=r"(r0), "=r"(r1), "=r"(r2), "=r"(r3) : "r"(addr))

#define LDSM4T(r0, r1, r2, r3, addr) \
    asm volatile("ldmatrix.sync.aligned.m8n8.x4.trans.shared.b16 {%0,%1,%2,%3}, [%4];" \
                 : "=r"(r0), "=r"(r1), "=r"(r2), "=r"(r3) : "r"(addr))

#define MMA16816(d, a0, a1, a2, a3, b0, b1) \
    asm volatile("mma.sync.aligned.m16n8k16.row.col.f32.bf16.bf16.f32 " \
                 "{%0,%1,%2,%3}, {%4,%5,%6,%7}, {%8,%9}, {%0,%1,%2,%3};" \
                 : "+f"((d)[0]), "+f"((d)[1]), "+f"((d)[2]), "+f"((d)[3]) \
                 : "r"(a0), "r"(a1), "r"(a2), "r"(a3), "r"(b0), "r"(b1))

__device__ __forceinline__ uint32_t pack_bf16(float a, float b) {
    __nv_bfloat162 v = __halves2bfloat162(__float2bfloat16(a), __float2bfloat16(b));
    return *(uint32_t*)&v;
}

__device__ __forceinline__ void store_split2(__nv_bfloat16* H, __nv_bfloat16* L,
                                             size_t idx, float a, float b) {
    __nv_bfloat16 ha = __float2bfloat16(a), hb = __float2bfloat16(b);
    float ra = a - __bfloat162float(ha), rb = b - __bfloat162float(hb);
    *(__nv_bfloat162*)(H + idx) = __halves2bfloat162(ha, hb);
    *(__nv_bfloat162*)(L + idx) =
        __halves2bfloat162(__float2bfloat16(ra), __float2bfloat16(rb));
}

// ====================== bf16 split conversion ================================
__global__ void split_kernel(const float4* __restrict__ src,
                             __nv_bfloat162* __restrict__ hi,
                             __nv_bfloat162* __restrict__ lo, int n4)
{
    int i = blockIdx.x * blockDim.x + threadIdx.x;
    if (i >= n4) return;
    float4 v = src[i];
    __nv_bfloat16 h0 = __float2bfloat16(v.x);
    __nv_bfloat16 h1 = __float2bfloat16(v.y);
    __nv_bfloat16 h2 = __float2bfloat16(v.z);
    __nv_bfloat16 h3 = __float2bfloat16(v.w);
    float r0 = v.x - __bfloat162float(h0);
    float r1 = v.y - __bfloat162float(h1);
    float r2 = v.z - __bfloat162float(h2);
    float r3 = v.w - __bfloat162float(h3);
    hi[2*i]   = __halves2bfloat162(h0, h1);
    hi[2*i+1] = __halves2bfloat162(h2, h3);
    lo[2*i]   = __halves2bfloat162(__float2bfloat16(r0), __float2bfloat16(r1));
    lo[2*i+1] = __halves2bfloat162(__float2bfloat16(r2), __float2bfloat16(r3));
}

// ====================== mma.sync split-bf16 GEMM ==============================
#define TB 16384
#define STAGE (4*TB)
#define GEMM_SMEM (2*STAGE)
#define NCK 16

__device__ __forceinline__ void stage_load(uint32_t sb,
    const uint4* __restrict__ Ah, const uint4* __restrict__ Al,
    const uint4* __restrict__ Bh, const uint4* __restrict__ Bl,
    int m0, int n0, int c, int tid)
{
    const int q = tid & 7;
    const int r0 = tid >> 3;
#pragma unroll
    for (int it = 0; it < 4; it++) {
        int row = r0 + it * 32;
        uint32_t off = row * 128 + q * 16;
        off ^= (off >> 3) & 0x70;
        size_t ga = (size_t)(m0 + row) * 128 + c * 8 + q;
        size_t gb = (size_t)(n0 + row) * 128 + c * 8 + q;
        cp16(sb + off,          Ah + ga);
        cp16(sb + TB + off,     Al + ga);
        cp16(sb + 2*TB + off,   Bh + gb);
        cp16(sb + 3*TB + off,   Bl + gb);
    }
}

__global__ void __launch_bounds__(256) mma_gemm(const __nv_bfloat16* __restrict__ Ah_,
                                                const __nv_bfloat16* __restrict__ Al_,
                                                const __nv_bfloat16* __restrict__ Bh_,
                                                const __nv_bfloat16* __restrict__ Bl_,
                                                float* __restrict__ C)
{
    extern __shared__ char smem[];
    const uint32_t sbase = smem_to_u32(smem);
    const int tid = threadIdx.x;
    const int wid = tid >> 5;
    const int lane = tid & 31;
    const int m0 = blockIdx.y * 128;
    const int n0 = blockIdx.x * 128;
    const int wm = (wid & 1) * 64;
    const int wn = (wid >> 1) * 32;

    const int t  = lane >> 3;
    const int li = lane & 7;
    const int arow  = (t & 1) * 8 + li;
    const int acolb = (t >> 1) * 16;
    const int brow  = ((t >> 1) & 1) * 8 + li;
    const int bcolb = (t & 1) * 16;

    const uint4* A4h = (const uint4*)Ah_;
    const uint4* A4l = (const uint4*)Al_;
    const uint4* B4h = (const uint4*)Bh_;
    const uint4* B4l = (const uint4*)Bl_;

    float acc[4][4][4];
#pragma unroll
    for (int i = 0; i < 4; i++)
#pragma unroll
        for (int j = 0; j < 4; j++)
#pragma unroll
            for (int r = 0; r < 4; r++) acc[i][j][r] = 0.f;

    stage_load(sbase, A4h, A4l, B4h, B4l, m0, n0, 0, tid);
    asm volatile("cp.async.commit_group;" ::: "memory");

    for (int c = 0; c < NCK; c++) {
        __syncthreads();
        if (c + 1 < NCK) {
            stage_load(sbase + (uint32_t)((c + 1) & 1) * STAGE,
                       A4h, A4l, B4h, B4l, m0, n0, c + 1, tid);
            asm volatile("cp.async.commit_group;" ::: "memory");
            asm volatile("cp.async.wait_group 1;" ::: "memory");
        } else {
            asm volatile("cp.async.wait_group 0;" ::: "memory");
        }
        __syncthreads();

        const uint32_t sb  = sbase + (uint32_t)(c & 1) * STAGE;
        const uint32_t sAh = sb;
        const uint32_t sAl = sb + TB;
        const uint32_t sBh = sb + 2*TB;
        const uint32_t sBl = sb + 3*TB;

#pragma unroll
        for (int kk = 0; kk < 4; kk++) {
            uint32_t bh[4][2], bl[4][2];
#pragma unroll
            for (int nf2 = 0; nf2 < 2; nf2++) {
                uint32_t off = (uint32_t)(wn + nf2 * 16 + brow) * 128 + kk * 32 + bcolb;
                off ^= (off >> 3) & 0x70;
                LDSM4(bh[nf2*2+0][0], bh[nf2*2+0][1], bh[nf2*2+1][0], bh[nf2*2+1][1], sBh + off);
                LDSM4(bl[nf2*2+0][0], bl[nf2*2+0][1], bl[nf2*2+1][0], bl[nf2*2+1][1], sBl + off);
            }
#pragma unroll
            for (int mf = 0; mf < 4; mf++) {
                uint32_t off = (uint32_t)(wm + mf * 16 + arow) * 128 + kk * 32 + acolb;
                off ^= (off >> 3) & 0x70;
                uint32_t ah0, ah1, ah2, ah3, al0, al1, al2, al3;
                LDSM4(ah0, ah1, ah2, ah3, sAh + off);
                LDSM4(al0, al1, al2, al3, sAl + off);
#pragma unroll
                for (int nf = 0; nf < 4; nf++) {
                    MMA16816(acc[mf][nf], ah0, ah1, ah2, ah3, bh[nf][0], bh[nf][1]);
                    MMA16816(acc[mf][nf], ah0, ah1, ah2, ah3, bl[nf][0], bl[nf][1]);
                    MMA16816(acc[mf][nf], al0, al1, al2, al3, bh[nf][0], bh[nf][1]);
                }
            }
        }
    }

    const int g  = lane >> 2;
    const int tq = lane & 3;
#pragma unroll
    for (int mf = 0; mf < 4; mf++) {
#pragma unroll
        for (int nf = 0; nf < 4; nf++) {
            int rr = m0 + wm + mf * 16 + g;
            int cc = n0 + wn + nf * 8 + tq * 2;
            *(float2*)&C[(size_t)rr * DMODEL + cc]       = make_float2(acc[mf][nf][0], acc[mf][nf][1]);
            *(float2*)&C[(size_t)(rr + 8) * DMODEL + cc] = make_float2(acc[mf][nf][2], acc[mf][nf][3]);
        }
    }
}

// ---------------- RoPE + transpose; emits fp32 KV cache + bf16 splits --------
struct RopeTab { float hi[32]; float lo[32]; };

__global__ void rope_kernel(const float* __restrict__ qtmp,
                            const float* __restrict__ ktmp,
                            const float* __restrict__ vtmp,
                            float* __restrict__ kc,
                            float* __restrict__ vc,
                            __nv_bfloat16* __restrict__ qh, __nv_bfloat16* __restrict__ ql,
                            __nv_bfloat16* __restrict__ kh, __nv_bfloat16* __restrict__ kl,
                            __nv_bfloat16* __restrict__ vh, __nv_bfloat16* __restrict__ vl,
                            RopeTab tab)
{
    int i = blockIdx.x * blockDim.x + threadIdx.x;
    const int NPAIR = BATCH * SEQ * NHEADS * (HDIM / 2);
    if (i >= NPAIR) return;

    int p = i & 31;
    int h = (i >> 5) & (NHEADS - 1);
    int s = (i >> 9) & (SEQ - 1);
    int b = i >> 20;

    size_t src = ((size_t)(b * SEQ + s) * DMODEL + h * HDIM) + 2 * p;
    size_t dst = (((size_t)(b * NHEADS + h) * SEQ + s) * HDIM) + 2 * p;

    float fs = (float)s;
    float ang = fmaf(fs, tab.lo[p], fs * tab.hi[p]);
    float c, sn;
    sincosf(ang, &sn, &c);

    float q1 = qtmp[src], q2 = qtmp[src + 1];
    float qr1 = q1 * c - q2 * sn;
    float qr2 = q1 * sn + q2 * c;
    store_split2(qh, ql, dst, qr1, qr2);

    float k1 = ktmp[src], k2 = ktmp[src + 1];
    float kr1 = k1 * c - k2 * sn;
    float kr2 = k1 * sn + k2 * c;
    kc[dst] = kr1; kc[dst + 1] = kr2;
    store_split2(kh, kl, dst, kr1, kr2);

    float v1 = vtmp[src], v2 = vtmp[src + 1];
    vc[dst] = v1; vc[dst + 1] = v2;
    store_split2(vh, vl, dst, v1, v2);
}

// ---------------- tensor-core causal flash attention -------------------------
// Br=128 (8 warps x 16 rows), Bc=64. Split bf16 (3 MMA) for QK^T and P.V.
// Smem: Qh 16K | Ql 16K | 2 stages x (Kh 8K, Kl 8K, Vh 8K, Vl 8K)
#define FQH 0
#define FQL 16384
#define FST 32768
#define FSTAGE 32768
#define FLASH_SMEM (FST + 2*FSTAGE)   // 98304

__device__ __forceinline__ void flash_stage(uint32_t st,
    const uint4* __restrict__ Kh, const uint4* __restrict__ Kl,
    const uint4* __restrict__ Vh, const uint4* __restrict__ Vl,
    int k0, int tid)
{
#pragma unroll
    for (int half = 0; half < 2; half++) {
        int idx = tid + half * 256;      // 0..511
        int row = idx >> 3, q = idx & 7;
        uint32_t off = row * 128 + q * 16;
        off ^= (off >> 3) & 0x70;
        size_t g = (size_t)(k0 + row) * 8 + q;
        cp16(st + off,           Kh + g);
        cp16(st + 8192  + off,   Kl + g);
        cp16(st + 16384 + off,   Vh + g);
        cp16(st + 24576 + off,   Vl + g);
    }
}

__global__ void __launch_bounds__(256) flash_mma(
    const __nv_bfloat16* __restrict__ qh_, const __nv_bfloat16* __restrict__ ql_,
    const __nv_bfloat16* __restrict__ kh_, const __nv_bfloat16* __restrict__ kl_,
    const __nv_bfloat16* __restrict__ vh_, const __nv_bfloat16* __restrict__ vl_,
    __nv_bfloat16* __restrict__ Oh, __nv_bfloat16* __restrict__ Ol)
{
    extern __shared__ char smem[];
    const uint32_t sb = smem_to_u32(smem);
    const int tid = threadIdx.x;
    const int wid = tid >> 5;
    const int lane = tid & 31;
    const int qt = gridDim.x - 1 - blockIdx.x;   // heavy first
    const int h  = blockIdx.y;
    const int b  = blockIdx.z;
    const int q0 = qt * 128;
    const size_t head = (size_t)(b * NHEADS + h) * SEQ;

    const uint4* Qh4 = (const uint4*)qh_ + (head + q0) * 8;
    const uint4* Ql4 = (const uint4*)ql_ + (head + q0) * 8;
    const uint4* Kh4 = (const uint4*)kh_ + head * 8;
    const uint4* Kl4 = (const uint4*)kl_ + head * 8;
    const uint4* Vh4 = (const uint4*)vh_ + head * 8;
    const uint4* Vl4 = (const uint4*)vl_ + head * 8;

    // ldmatrix lane addressing
    const int t  = lane >> 3;
    const int li = lane & 7;
    const int arow  = (t & 1) * 8 + li;
    const int acolb = (t >> 1) * 16;
    const int brow  = ((t >> 1) & 1) * 8 + li;
    const int bcolb = (t & 1) * 16;
    // V (trans) addressing: row within k-group, col block select
    const int vrow  = (t & 1) * 8 + li;
    const int vcsel = (t >> 1);        // 0 or 1 -> n-block j + vcsel

    // load Q tile (hi+lo) via cp.async
#pragma unroll
    for (int it = 0; it < 4; it++) {
        int idx = tid + it * 256;       // 0..1023
        int row = idx >> 3, q = idx & 7;
        uint32_t off = row * 128 + q * 16;
        off ^= (off >> 3) & 0x70;
        cp16(sb + FQH + off, Qh4 + (size_t)row * 8 + q);
        cp16(sb + FQL + off, Ql4 + (size_t)row * 8 + q);
    }
    flash_stage(sb + FST, Kh4, Kl4, Vh4, Vl4, 0, tid);
    asm volatile("cp.async.commit_group;" ::: "memory");

    const int nkt = 2 * qt + 2;

    uint32_t qhA[4][4], qlA[4][4];
    float out[8][4];
#pragma unroll
    for (int nf = 0; nf < 8; nf++)
#pragma unroll
        for (int r = 0; r < 4; r++) out[nf][r] = 0.f;

    float m0 = -1e30f, m1 = -1e30f, l0 = 0.f, l1 = 0.f;
    const int r0g = q0 + wid * 16 + (lane >> 2);
    const int r1g = r0g + 8;

    for (int kt = 0; kt < nkt; kt++) {
        __syncthreads();
        if (kt + 1 < nkt) {
            flash_stage(sb + FST + (uint32_t)((kt + 1) & 1) * FSTAGE,
                        Kh4, Kl4, Vh4, Vl4, (kt + 1) * 64, tid);
            asm volatile("cp.async.commit_group;" ::: "memory");
            asm volatile("cp.async.wait_group 1;" ::: "memory");
        } else {
            asm volatile("cp.async.wait_group 0;" ::: "memory");
        }
        __syncthreads();

        if (kt == 0) {
            // Q fragments, register-resident for whole kernel
#pragma unroll
            for (int kk = 0; kk < 4; kk++) {
                uint32_t off = (uint32_t)(wid * 16 + arow) * 128 + kk * 32 + acolb;
                off ^= (off >> 3) & 0x70;
                LDSM4(qhA[kk][0], qhA[kk][1], qhA[kk][2], qhA[kk][3], sb + FQH + off);
                LDSM4(qlA[kk][0], qlA[kk][1], qlA[kk][2], qlA[kk][3], sb + FQL + off);
            }
        }

        const uint32_t st  = sb + FST + (uint32_t)(kt & 1) * FSTAGE;
        const uint32_t sKh = st, sKl = st + 8192, sVh = st + 16384, sVl = st + 24576;

        // ---- S = Q K^T ----
        float sacc[8][4];
#pragma unroll
        for (int nf = 0; nf < 8; nf++)
#pragma unroll
            for (int r = 0; r < 4; r++) sacc[nf][r] = 0.f;

#pragma unroll
        for (int kk = 0; kk < 4; kk++) {
#pragma unroll
            for (int nfp = 0; nfp < 4; nfp++) {
                uint32_t off = (uint32_t)(nfp * 16 + brow) * 128 + kk * 32 + bcolb;
                off ^= (off >> 3) & 0x70;
                uint32_t bh0, bh1, bh2, bh3, bl0, bl1, bl2, bl3;
                LDSM4(bh0, bh1, bh2, bh3, sKh + off);
                LDSM4(bl0, bl1, bl2, bl3, sKl + off);
                MMA16816(sacc[nfp*2],   qhA[kk][0], qhA[kk][1], qhA[kk][2], qhA[kk][3], bh0, bh1);
                MMA16816(sacc[nfp*2],   qhA[kk][0], qhA[kk][1], qhA[kk][2], qhA[kk][3], bl0, bl1);
                MMA16816(sacc[nfp*2],   qlA[kk][0], qlA[kk][1], qlA[kk][2], qlA[kk][3], bh0, bh1);
                MMA16816(sacc[nfp*2+1], qhA[kk][0], qhA[kk][1], qhA[kk][2], qhA[kk][3], bh2, bh3);
                MMA16816(sacc[nfp*2+1], qhA[kk][0], qhA[kk][1], qhA[kk][2], qhA[kk][3], bl2, bl3);
                MMA16816(sacc[nfp*2+1], qlA[kk][0], qlA[kk][1], qlA[kk][2], qlA[kk][3], bh2, bh3);
            }
        }

        // ---- scale + causal mask + online softmax ----
        const float sc = 0.125f;
        const bool domask = (kt >= nkt - 2);
        float mx0 = -1e30f, mx1 = -1e30f;
#pragma unroll
        for (int nf = 0; nf < 8; nf++) {
            int key = kt * 64 + nf * 8 + (lane & 3) * 2;
            float s0 = sacc[nf][0] * sc;
            float s1 = sacc[nf][1] * sc;
            float s2 = sacc[nf][2] * sc;
            float s3 = sacc[nf][3] * sc;
            if (domask) {
                if (key     > r0g) s0 = -1e30f;
                if (key + 1 > r0g) s1 = -1e30f;
                if (key     > r1g) s2 = -1e30f;
                if (key + 1 > r1g) s3 = -1e30f;
            }
            sacc[nf][0] = s0; sacc[nf][1] = s1; sacc[nf][2] = s2; sacc[nf][3] = s3;
            mx0 = fmaxf(mx0, fmaxf(s0, s1));
            mx1 = fmaxf(mx1, fmaxf(s2, s3));
        }
        mx0 = fmaxf(mx0, __shfl_xor_sync(0xffffffffu, mx0, 1));
        mx0 = fmaxf(mx0, __shfl_xor_sync(0xffffffffu, mx0, 2));
        mx1 = fmaxf(mx1, __shfl_xor_sync(0xffffffffu, mx1, 1));
        mx1 = fmaxf(mx1, __shfl_xor_sync(0xffffffffu, mx1, 2));

        float mn0 = fmaxf(m0, mx0), mn1 = fmaxf(m1, mx1);
        float al0 = __expf(m0 - mn0), al1 = __expf(m1 - mn1);

        uint32_t phA[4][4], plA[4][4];
        float sum0 = 0.f, sum1 = 0.f;
#pragma unroll
        for (int nf = 0; nf < 8; nf++) {
            float p0 = __expf(sacc[nf][0] - mn0);
            float p1 = __expf(sacc[nf][1] - mn0);
            float p2 = __expf(sacc[nf][2] - mn1);
            float p3 = __expf(sacc[nf][3] - mn1);
            sum0 += p0 + p1;
            sum1 += p2 + p3;
            // bf16 hi/lo split, packed into A-fragment layout
            __nv_bfloat16 h0 = __float2bfloat16(p0), h1 = __float2bfloat16(p1);
            __nv_bfloat16 h2 = __float2bfloat16(p2), h3 = __float2bfloat16(p3);
            float e0 = p0 - __bfloat162float(h0), e1 = p1 - __bfloat162float(h1);
            float e2 = p2 - __bfloat162float(h2), e3 = p3 - __bfloat162float(h3);
            int kk = nf >> 1;
            int rb = (nf & 1) * 2;
            __nv_bfloat162 ph01 = __halves2bfloat162(h0, h1);
            __nv_bfloat162 ph23 = __halves2bfloat162(h2, h3);
            phA[kk][rb]     = *(uint32_t*)&ph01;
            phA[kk][rb + 1] = *(uint32_t*)&ph23;
            plA[kk][rb]     = pack_bf16(e0, e1);
            plA[kk][rb + 1] = pack_bf16(e2, e3);
        }
        sum0 += __shfl_xor_sync(0xffffffffu, sum0, 1);
        sum0 += __shfl_xor_sync(0xffffffffu, sum0, 2);
        sum1 += __shfl_xor_sync(0xffffffffu, sum1, 1);
        sum1 += __shfl_xor_sync(0xffffffffu, sum1, 2);
        l0 = l0 * al0 + sum0;
        l1 = l1 * al1 + sum1;
        m0 = mn0; m1 = mn1;

        // rescale accumulators
#pragma unroll
        for (int nf = 0; nf < 8; nf++) {
            out[nf][0] *= al0; out[nf][1] *= al0;
            out[nf][2] *= al1; out[nf][3] *= al1;
        }

        // ---- O += P V ----
#pragma unroll
        for (int kk = 0; kk < 4; kk++) {
#pragma unroll
            for (int jp = 0; jp < 8; jp += 2) {
                uint32_t off = (uint32_t)(kk * 16 + vrow) * 128 + (jp + vcsel) * 16;
                off ^= (off >> 3) & 0x70;
                uint32_t vh0, vh1, vh2, vh3, vl0, vl1, vl2, vl3;
                LDSM4T(vh0, vh1, vh2, vh3, sVh + off);
                LDSM4T(vl0, vl1, vl2, vl3, sVl + off);
                MMA16816(out[jp],   phA[kk][0], phA[kk][1], phA[kk][2], phA[kk][3], vh0, vh1);
                MMA16816(out[jp],   phA[kk][0], phA[kk][1], phA[kk][2], phA[kk][3], vl0, vl1);
                MMA16816(out[jp],   plA[kk][0], plA[kk][1], plA[kk][2], plA[kk][3], vh0, vh1);
                MMA16816(out[jp+1], phA[kk][0], phA[kk][1], phA[kk][2], phA[kk][3], vh2, vh3);
                MMA16816(out[jp+1], phA[kk][0], phA[kk][1], phA[kk][2], phA[kk][3], vl2, vl3);
                MMA16816(out[jp+1], plA[kk][0], plA[kk][1], plA[kk][2], plA[kk][3], vh2, vh3);
            }
        }
    }

    // ---- epilogue: normalize, split-bf16 store into [B,S,D] ----
    float inv0 = 1.f / l0, inv1 = 1.f / l1;
#pragma unroll
    for (int nf = 0; nf < 8; nf++) {
        int col = h * HDIM + nf * 8 + (lane & 3) * 2;
        size_t i0 = (size_t)(b * SEQ + r0g) * DMODEL + col;
        size_t i1 = (size_t)(b * SEQ + r1g) * DMODEL + col;
        store_split2(Oh, Ol, i0, out[nf][0] * inv0, out[nf][1] * inv0);
        store_split2(Oh, Ol, i1, out[nf][2] * inv1, out[nf][3] * inv1);
    }
}

// ---------------- launcher ---------------------------------------------------
extern "C" void kernel_launch(void* const* d_in, const int* in_sizes, int n_in,
                              void* d_out, int out_size)
{
    const float* x  = (const float*)d_in[0];
    const float* Wq = (const float*)d_in[2];
    const float* Wk = (const float*)d_in[3];
    const float* Wv = (const float*)d_in[4];
    const float* Wo = (const float*)d_in[5];
    float* out = (float*)d_out;

    float *qtmp, *ktmp, *vtmp, *kfb, *vfb;
    cudaGetSymbolAddress((void**)&qtmp, g_qtmp);
    cudaGetSymbolAddress((void**)&ktmp, g_ktmp);
    cudaGetSymbolAddress((void**)&vtmp, g_vtmp);
    cudaGetSymbolAddress((void**)&kfb,  g_kfb);
    cudaGetSymbolAddress((void**)&vfb,  g_vfb);

    __nv_bfloat16 *xh, *xl, *wqh, *wql, *wkh, *wkl, *wvh, *wvl, *woh, *wol;
    __nv_bfloat16 *qh, *ql, *kh, *kl, *vh, *vl;
    cudaGetSymbolAddress((void**)&xh, g_xh);
    cudaGetSymbolAddress((void**)&xl, g_xl);
    cudaGetSymbolAddress((void**)&wqh, g_wqh);
    cudaGetSymbolAddress((void**)&wql, g_wql);
    cudaGetSymbolAddress((void**)&wkh, g_wkh);
    cudaGetSymbolAddress((void**)&wkl, g_wkl);
    cudaGetSymbolAddress((void**)&wvh, g_wvh);
    cudaGetSymbolAddress((void**)&wvl, g_wvl);
    cudaGetSymbolAddress((void**)&woh, g_woh);
    cudaGetSymbolAddress((void**)&wol, g_wol);
    cudaGetSymbolAddress((void**)&qh, g_qh);
    cudaGetSymbolAddress((void**)&ql, g_ql);
    cudaGetSymbolAddress((void**)&kh, g_kh);
    cudaGetSymbolAddress((void**)&kl, g_kl);
    cudaGetSymbolAddress((void**)&vh, g_vh);
    cudaGetSymbolAddress((void**)&vl, g_vl);

    float* kdst;
    float* vdst;
    if (out_size >= OUTN + 2 * KVN) {
        kdst = out + OUTN;
        vdst = out + OUTN + KVN;
    } else {
        kdst = kfb;
        vdst = vfb;
    }

    cudaFuncSetAttribute(mma_gemm, cudaFuncAttributeMaxDynamicSharedMemorySize, GEMM_SMEM);
    cudaFuncSetAttribute(flash_mma, cudaFuncAttributeMaxDynamicSharedMemorySize, FLASH_SMEM);

    RopeTab tab;
    for (int p = 0; p < 32; p++) {
        double invf = exp(-(double)p * (log(10000.0) / 32.0));
        float hi = (float)invf;
        tab.hi[p] = hi;
        tab.lo[p] = (float)(invf - (double)hi);
    }

    // bf16 splits of inputs
    split_kernel<<<OUTN/4/256, 256>>>((const float4*)x, (__nv_bfloat162*)xh, (__nv_bfloat162*)xl, OUTN/4);
    split_kernel<<<WN/4/256, 256>>>((const float4*)Wq, (__nv_bfloat162*)wqh, (__nv_bfloat162*)wql, WN/4);
    split_kernel<<<WN/4/256, 256>>>((const float4*)Wk, (__nv_bfloat162*)wkh, (__nv_bfloat162*)wkl, WN/4);
    split_kernel<<<WN/4/256, 256>>>((const float4*)Wv, (__nv_bfloat162*)wvh, (__nv_bfloat162*)wvl, WN/4);
    split_kernel<<<WN/4/256, 256>>>((const float4*)Wo, (__nv_bfloat162*)woh, (__nv_bfloat162*)wol, WN/4);

    // projections on tensor cores
    dim3 ggrid(DMODEL / 128, MROWS / 128);   // (8, 32)
    mma_gemm<<<ggrid, 256, GEMM_SMEM>>>(xh, xl, wqh, wql, qtmp);
    mma_gemm<<<ggrid, 256, GEMM_SMEM>>>(xh, xl, wkh, wkl, ktmp);
    mma_gemm<<<ggrid, 256, GEMM_SMEM>>>(xh, xl, wvh, wvl, vtmp);

    const int NPAIR = BATCH * SEQ * NHEADS * (HDIM / 2);
    rope_kernel<<<(NPAIR + 255) / 256, 256>>>(qtmp, ktmp, vtmp, kdst, vdst,
                                              qh, ql, kh, kl, vh, vl, tab);

    // tensor-core flash attention -> split bf16 attn output (xh/xl reused)
    dim3 fgrid(SEQ / 128, NHEADS, BATCH);    // (16, 16, 2)
    flash_mma<<<fgrid, 256, FLASH_SMEM>>>(qh, ql, kh, kl, vh, vl, xh, xl);

    // output projection
    mma_gemm<<<ggrid, 256, GEMM_SMEM>>>(xh, xl, woh, wol, out);
}

// round 5
// speedup vs baseline: 5.4079x; 1.0490x over previous
#include <cuda_runtime.h>
#include <cuda_bf16.h>
#include <math.h>
#include <stdint.h>

// Problem constants
#define BATCH 2
#define SEQ 2048
#define DMODEL 1024
#define NHEADS 16
#define HDIM 64
#define MROWS (BATCH*SEQ)              // 4096
#define OUTN  (BATCH*SEQ*DMODEL)       // 4194304
#define KVN   (BATCH*NHEADS*SEQ*HDIM)  // 4194304
#define WN    (DMODEL*DMODEL)          // 1048576

// ---------------- scratch (device globals; no allocations allowed) ----------
__device__ float g_kfb[KVN];
__device__ float g_vfb[KVN];
__device__ __nv_bfloat16 g_xh[OUTN];
__device__ __nv_bfloat16 g_xl[OUTN];
__device__ __nv_bfloat16 g_wqh[WN], g_wql[WN];
__device__ __nv_bfloat16 g_wkh[WN], g_wkl[WN];
__device__ __nv_bfloat16 g_wvh[WN], g_wvl[WN];
__device__ __nv_bfloat16 g_woh[WN], g_wol[WN];
__device__ __nv_bfloat16 g_qh[KVN], g_ql[KVN];
__device__ __nv_bfloat16 g_kh[KVN], g_kl[KVN];
__device__ __nv_bfloat16 g_vh[KVN], g_vl[KVN];

// ====================== helpers ==============================================
__device__ __forceinline__ uint32_t smem_to_u32(const void* p) {
    uint32_t a;
    asm("{ .reg .u64 t; cvta.to.shared.u64 t, %1; cvt.u32.u64 %0, t; }"
        : "=r"(a) : "l"(p));
    return a;
}

__device__ __forceinline__ void cp16(uint32_t saddr, const void* g) {
    asm volatile("cp.async.cg.shared.global [%0], [%1], 16;"
                 :: "r"(saddr), "l"(g) : "memory");
}

#define LDSM4(r0, r1, r2, r3, addr) \
    asm volatile("ldmatrix.sync.aligned.m8n8.x4.shared.b16 {%0,%1,%2,%3}, [%4];" \
                 : "=r"(r0), "=r"(r1), "=r"(r2), "=r"(r3) : "r"(addr))

#define LDSM4T(r0, r1, r2, r3, addr) \
    asm volatile("ldmatrix.sync.aligned.m8n8.x4.trans.shared.b16 {%0,%1,%2,%3}, [%4];" \
                 : "=r"(r0), "=r"(r1), "=r"(r2), "=r"(r3) : "r"(addr))

#define MMA16816(d, a0, a1, a2, a3, b0, b1) \
    asm volatile("mma.sync.aligned.m16n8k16.row.col.f32.bf16.bf16.f32 " \
                 "{%0,%1,%2,%3}, {%4,%5,%6,%7}, {%8,%9}, {%0,%1,%2,%3};" \
                 : "+f"((d)[0]), "+f"((d)[1]), "+f"((d)[2]), "+f"((d)[3]) \
                 : "r"(a0), "r"(a1), "r"(a2), "r"(a3), "r"(b0), "r"(b1))

__device__ __forceinline__ uint32_t pack_bf16(float a, float b) {
    __nv_bfloat162 v = __halves2bfloat162(__float2bfloat16(a), __float2bfloat16(b));
    return *(uint32_t*)&v;
}

__device__ __forceinline__ void store_split2(__nv_bfloat16* H, __nv_bfloat16* L,
                                             size_t idx, float a, float b) {
    __nv_bfloat16 ha = __float2bfloat16(a), hb = __float2bfloat16(b);
    float ra = a - __bfloat162float(ha), rb = b - __bfloat162float(hb);
    *(__nv_bfloat162*)(H + idx) = __halves2bfloat162(ha, hb);
    *(__nv_bfloat162*)(L + idx) =
        __halves2bfloat162(__float2bfloat16(ra), __float2bfloat16(rb));
}

struct RopeTab { float hi[32]; float lo[32]; };

// ====================== bf16 split conversion ================================
__global__ void split_kernel(const float4* __restrict__ src,
                             __nv_bfloat162* __restrict__ hi,
                             __nv_bfloat162* __restrict__ lo, int n4)
{
    int i = blockIdx.x * blockDim.x + threadIdx.x;
    if (i >= n4) return;
    float4 v = src[i];
    __nv_bfloat16 h0 = __float2bfloat16(v.x);
    __nv_bfloat16 h1 = __float2bfloat16(v.y);
    __nv_bfloat16 h2 = __float2bfloat16(v.z);
    __nv_bfloat16 h3 = __float2bfloat16(v.w);
    float r0 = v.x - __bfloat162float(h0);
    float r1 = v.y - __bfloat162float(h1);
    float r2 = v.z - __bfloat162float(h2);
    float r3 = v.w - __bfloat162float(h3);
    hi[2*i]   = __halves2bfloat162(h0, h1);
    hi[2*i+1] = __halves2bfloat162(h2, h3);
    lo[2*i]   = __halves2bfloat162(__float2bfloat16(r0), __float2bfloat16(r1));
    lo[2*i+1] = __halves2bfloat162(__float2bfloat16(r2), __float2bfloat16(r3));
}

struct Ptrs4 {
    const float4* s[4];
    __nv_bfloat162* h[4];
    __nv_bfloat162* l[4];
};

__global__ void wsplit(Ptrs4 p, int n4)
{
    int i = blockIdx.x * blockDim.x + threadIdx.x;
    int w = blockIdx.y;
    if (i >= n4) return;
    float4 v = p.s[w][i];
    __nv_bfloat16 h0 = __float2bfloat16(v.x);
    __nv_bfloat16 h1 = __float2bfloat16(v.y);
    __nv_bfloat16 h2 = __float2bfloat16(v.z);
    __nv_bfloat16 h3 = __float2bfloat16(v.w);
    float r0 = v.x - __bfloat162float(h0);
    float r1 = v.y - __bfloat162float(h1);
    float r2 = v.z - __bfloat162float(h2);
    float r3 = v.w - __bfloat162float(h3);
    p.h[w][2*i]   = __halves2bfloat162(h0, h1);
    p.h[w][2*i+1] = __halves2bfloat162(h2, h3);
    p.l[w][2*i]   = __halves2bfloat162(__float2bfloat16(r0), __float2bfloat16(r1));
    p.l[w][2*i+1] = __halves2bfloat162(__float2bfloat16(r2), __float2bfloat16(r3));
}

// ====================== mma.sync split-bf16 GEMM core =========================
#define TB 16384
#define STAGE (4*TB)
#define GEMM_SMEM (2*STAGE)
#define NCK 16

__device__ __forceinline__ void stage_load(uint32_t sb,
    const uint4* __restrict__ Ah, const uint4* __restrict__ Al,
    const uint4* __restrict__ Bh, const uint4* __restrict__ Bl,
    int m0, int n0, int c, int tid)
{
    const int q = tid & 7;
    const int r0 = tid >> 3;
#pragma unroll
    for (int it = 0; it < 4; it++) {
        int row = r0 + it * 32;
        uint32_t off = row * 128 + q * 16;
        off ^= (off >> 3) & 0x70;
        size_t ga = (size_t)(m0 + row) * 128 + c * 8 + q;
        size_t gb = (size_t)(n0 + row) * 128 + c * 8 + q;
        cp16(sb + off,          Ah + ga);
        cp16(sb + TB + off,     Al + ga);
        cp16(sb + 2*TB + off,   Bh + gb);
        cp16(sb + 3*TB + off,   Bl + gb);
    }
}

// shared mainloop: computes acc for a 128x128 tile
__device__ __forceinline__ void gemm_mainloop(uint32_t sbase,
    const uint4* A4h, const uint4* A4l, const uint4* B4h, const uint4* B4l,
    int m0, int n0, int tid, int wm, int wn,
    int arow, int acolb, int brow, int bcolb, float acc[4][4][4])
{
#pragma unroll
    for (int i = 0; i < 4; i++)
#pragma unroll
        for (int j = 0; j < 4; j++)
#pragma unroll
            for (int r = 0; r < 4; r++) acc[i][j][r] = 0.f;

    stage_load(sbase, A4h, A4l, B4h, B4l, m0, n0, 0, tid);
    asm volatile("cp.async.commit_group;" ::: "memory");

    for (int c = 0; c < NCK; c++) {
        __syncthreads();
        if (c + 1 < NCK) {
            stage_load(sbase + (uint32_t)((c + 1) & 1) * STAGE,
                       A4h, A4l, B4h, B4l, m0, n0, c + 1, tid);
            asm volatile("cp.async.commit_group;" ::: "memory");
            asm volatile("cp.async.wait_group 1;" ::: "memory");
        } else {
            asm volatile("cp.async.wait_group 0;" ::: "memory");
        }
        __syncthreads();

        const uint32_t sb  = sbase + (uint32_t)(c & 1) * STAGE;
        const uint32_t sAh = sb;
        const uint32_t sAl = sb + TB;
        const uint32_t sBh = sb + 2*TB;
        const uint32_t sBl = sb + 3*TB;

#pragma unroll
        for (int kk = 0; kk < 4; kk++) {
            uint32_t bh[4][2], bl[4][2];
#pragma unroll
            for (int nf2 = 0; nf2 < 2; nf2++) {
                uint32_t off = (uint32_t)(wn + nf2 * 16 + brow) * 128 + kk * 32 + bcolb;
                off ^= (off >> 3) & 0x70;
                LDSM4(bh[nf2*2+0][0], bh[nf2*2+0][1], bh[nf2*2+1][0], bh[nf2*2+1][1], sBh + off);
                LDSM4(bl[nf2*2+0][0], bl[nf2*2+0][1], bl[nf2*2+1][0], bl[nf2*2+1][1], sBl + off);
            }
#pragma unroll
            for (int mf = 0; mf < 4; mf++) {
                uint32_t off = (uint32_t)(wm + mf * 16 + arow) * 128 + kk * 32 + acolb;
                off ^= (off >> 3) & 0x70;
                uint32_t ah0, ah1, ah2, ah3, al0, al1, al2, al3;
                LDSM4(ah0, ah1, ah2, ah3, sAh + off);
                LDSM4(al0, al1, al2, al3, sAl + off);
#pragma unroll
                for (int nf = 0; nf < 4; nf++) {
                    MMA16816(acc[mf][nf], ah0, ah1, ah2, ah3, bh[nf][0], bh[nf][1]);
                    MMA16816(acc[mf][nf], ah0, ah1, ah2, ah3, bl[nf][0], bl[nf][1]);
                    MMA16816(acc[mf][nf], al0, al1, al2, al3, bh[nf][0], bh[nf][1]);
                }
            }
        }
    }
}

// -------- plain GEMM (output projection): C fp32 [M,N] -----------------------
__global__ void __launch_bounds__(256) mma_gemm(const __nv_bfloat16* __restrict__ Ah_,
                                                const __nv_bfloat16* __restrict__ Al_,
                                                const __nv_bfloat16* __restrict__ Bh_,
                                                const __nv_bfloat16* __restrict__ Bl_,
                                                float* __restrict__ C)
{
    extern __shared__ char smem[];
    const uint32_t sbase = smem_to_u32(smem);
    const int tid = threadIdx.x;
    const int wid = tid >> 5;
    const int lane = tid & 31;
    const int m0 = blockIdx.y * 128;
    const int n0 = blockIdx.x * 128;
    const int wm = (wid & 1) * 64;
    const int wn = (wid >> 1) * 32;
    const int t  = lane >> 3;
    const int li = lane & 7;

    float acc[4][4][4];
    gemm_mainloop(sbase, (const uint4*)Ah_, (const uint4*)Al_,
                  (const uint4*)Bh_, (const uint4*)Bl_,
                  m0, n0, tid, wm, wn,
                  (t & 1) * 8 + li, (t >> 1) * 16,
                  ((t >> 1) & 1) * 8 + li, (t & 1) * 16, acc);

    const int g  = lane >> 2;
    const int tq = lane & 3;
#pragma unroll
    for (int mf = 0; mf < 4; mf++) {
#pragma unroll
        for (int nf = 0; nf < 4; nf++) {
            int rr = m0 + wm + mf * 16 + g;
            int cc = n0 + wn + nf * 8 + tq * 2;
            *(float2*)&C[(size_t)rr * DMODEL + cc]       = make_float2(acc[mf][nf][0], acc[mf][nf][1]);
            *(float2*)&C[(size_t)(rr + 8) * DMODEL + cc] = make_float2(acc[mf][nf][2], acc[mf][nf][3]);
        }
    }
}

// -------- fused QKV GEMM + RoPE + transpose + bf16 split ---------------------
// blockIdx.z: 0=Q (rotate), 1=K (rotate + fp32 cache), 2=V (fp32 cache)
__global__ void __launch_bounds__(256) qkv_gemm(
    const __nv_bfloat16* __restrict__ xh_, const __nv_bfloat16* __restrict__ xl_,
    const __nv_bfloat16* __restrict__ wqh_, const __nv_bfloat16* __restrict__ wql_,
    const __nv_bfloat16* __restrict__ wkh_, const __nv_bfloat16* __restrict__ wkl_,
    const __nv_bfloat16* __restrict__ wvh_, const __nv_bfloat16* __restrict__ wvl_,
    __nv_bfloat16* __restrict__ qh, __nv_bfloat16* __restrict__ ql,
    __nv_bfloat16* __restrict__ kh, __nv_bfloat16* __restrict__ kl,
    __nv_bfloat16* __restrict__ vh, __nv_bfloat16* __restrict__ vl,
    float* __restrict__ kc, float* __restrict__ vc, RopeTab tab)
{
    extern __shared__ char smem[];
    const uint32_t sbase = smem_to_u32(smem);
    const int tid = threadIdx.x;
    const int wid = tid >> 5;
    const int lane = tid & 31;
    const int m0 = blockIdx.y * 128;
    const int n0 = blockIdx.x * 128;
    const int which = blockIdx.z;
    const int wm = (wid & 1) * 64;
    const int wn = (wid >> 1) * 32;
    const int t  = lane >> 3;
    const int li = lane & 7;

    const __nv_bfloat16* Bh_ = (which == 0) ? wqh_ : (which == 1) ? wkh_ : wvh_;
    const __nv_bfloat16* Bl_ = (which == 0) ? wql_ : (which == 1) ? wkl_ : wvl_;

    float acc[4][4][4];
    gemm_mainloop(sbase, (const uint4*)xh_, (const uint4*)xl_,
                  (const uint4*)Bh_, (const uint4*)Bl_,
                  m0, n0, tid, wm, wn,
                  (t & 1) * 8 + li, (t >> 1) * 16,
                  ((t >> 1) & 1) * 8 + li, (t & 1) * 16, acc);

    __nv_bfloat16* H = (which == 0) ? qh : (which == 1) ? kh : vh;
    __nv_bfloat16* L = (which == 0) ? ql : (which == 1) ? kl : vl;

    const int g  = lane >> 2;
    const int tq = lane & 3;
#pragma unroll
    for (int mf = 0; mf < 4; mf++) {
#pragma unroll
        for (int nf = 0; nf < 4; nf++) {
            int cc = n0 + wn + nf * 8 + tq * 2;
            int hh = cc >> 6;
            int d  = cc & 63;
            int p  = d >> 1;
            float fhi = tab.hi[p], flo = tab.lo[p];
#pragma unroll
            for (int r = 0; r < 2; r++) {
                int rr = m0 + wm + mf * 16 + g + r * 8;
                float a = acc[mf][nf][r*2], bv = acc[mf][nf][r*2+1];
                int s  = rr & (SEQ - 1);
                int bb = rr >> 11;
                if (which != 2) {
                    float fs = (float)s;
                    float ang = fmaf(fs, flo, fs * fhi);
                    float c, sn;
                    sincosf(ang, &sn, &c);
                    float na = a * c - bv * sn;
                    float nb = a * sn + bv * c;
                    a = na; bv = nb;
                }
                size_t dst = ((size_t)(bb * NHEADS + hh) * SEQ + s) * HDIM + d;
                store_split2(H, L, dst, a, bv);
                if (which == 1) *(float2*)(kc + dst) = make_float2(a, bv);
                if (which == 2) *(float2*)(vc + dst) = make_float2(a, bv);
            }
        }
    }
}

// ---------------- tensor-core causal flash attention (Bc=128) ----------------
#define FQH 0
#define FQL 16384
#define FST 32768
#define FSTAGE 65536
#define FLASH_SMEM (FST + 2*FSTAGE)   // 163840

__device__ __forceinline__ void flash_stage(uint32_t st,
    const uint4* __restrict__ Kh, const uint4* __restrict__ Kl,
    const uint4* __restrict__ Vh, const uint4* __restrict__ Vl,
    int k0, int tid)
{
#pragma unroll
    for (int it = 0; it < 4; it++) {
        int idx = tid + it * 256;        // 0..1023
        int row = idx >> 3, q = idx & 7;
        uint32_t off = row * 128 + q * 16;
        off ^= (off >> 3) & 0x70;
        size_t g = (size_t)(k0 + row) * 8 + q;
        cp16(st + off,           Kh + g);
        cp16(st + 16384 + off,   Kl + g);
        cp16(st + 32768 + off,   Vh + g);
        cp16(st + 49152 + off,   Vl + g);
    }
}

__global__ void __launch_bounds__(256, 1) flash_mma(
    const __nv_bfloat16* __restrict__ qh_, const __nv_bfloat16* __restrict__ ql_,
    const __nv_bfloat16* __restrict__ kh_, const __nv_bfloat16* __restrict__ kl_,
    const __nv_bfloat16* __restrict__ vh_, const __nv_bfloat16* __restrict__ vl_,
    __nv_bfloat16* __restrict__ Oh, __nv_bfloat16* __restrict__ Ol)
{
    extern __shared__ char smem[];
    const uint32_t sb = smem_to_u32(smem);
    const int tid = threadIdx.x;
    const int wid = tid >> 5;
    const int lane = tid & 31;
    const int qt = gridDim.x - 1 - blockIdx.x;   // heavy first
    const int h  = blockIdx.y;
    const int b  = blockIdx.z;
    const int q0 = qt * 128;
    const size_t head = (size_t)(b * NHEADS + h) * SEQ;

    const uint4* Qh4 = (const uint4*)qh_ + (head + q0) * 8;
    const uint4* Ql4 = (const uint4*)ql_ + (head + q0) * 8;
    const uint4* Kh4 = (const uint4*)kh_ + head * 8;
    const uint4* Kl4 = (const uint4*)kl_ + head * 8;
    const uint4* Vh4 = (const uint4*)vh_ + head * 8;
    const uint4* Vl4 = (const uint4*)vl_ + head * 8;

    const int t  = lane >> 3;
    const int li = lane & 7;
    const int arow  = (t & 1) * 8 + li;
    const int acolb = (t >> 1) * 16;
    const int brow  = ((t >> 1) & 1) * 8 + li;
    const int bcolb = (t & 1) * 16;
    const int vrow  = (t & 1) * 8 + li;
    const int vcsel = (t >> 1);

    // Q tile (hi+lo)
#pragma unroll
    for (int it = 0; it < 4; it++) {
        int idx = tid + it * 256;
        int row = idx >> 3, q = idx & 7;
        uint32_t off = row * 128 + q * 16;
        off ^= (off >> 3) & 0x70;
        cp16(sb + FQH + off, Qh4 + (size_t)row * 8 + q);
        cp16(sb + FQL + off, Ql4 + (size_t)row * 8 + q);
    }
    flash_stage(sb + FST, Kh4, Kl4, Vh4, Vl4, 0, tid);
    asm volatile("cp.async.commit_group;" ::: "memory");

    const int nkt = qt + 1;

    uint32_t qhA[4][4], qlA[4][4];
    float out[8][4];
#pragma unroll
    for (int nf = 0; nf < 8; nf++)
#pragma unroll
        for (int r = 0; r < 4; r++) out[nf][r] = 0.f;

    float m0 = -1e30f, m1 = -1e30f, l0 = 0.f, l1 = 0.f;
    const int r0g = q0 + wid * 16 + (lane >> 2);
    const int r1g = r0g + 8;

    for (int kt = 0; kt < nkt; kt++) {
        __syncthreads();
        if (kt + 1 < nkt) {
            flash_stage(sb + FST + (uint32_t)((kt + 1) & 1) * FSTAGE,
                        Kh4, Kl4, Vh4, Vl4, (kt + 1) * 128, tid);
            asm volatile("cp.async.commit_group;" ::: "memory");
            asm volatile("cp.async.wait_group 1;" ::: "memory");
        } else {
            asm volatile("cp.async.wait_group 0;" ::: "memory");
        }
        __syncthreads();

        if (kt == 0) {
#pragma unroll
            for (int kk = 0; kk < 4; kk++) {
                uint32_t off = (uint32_t)(wid * 16 + arow) * 128 + kk * 32 + acolb;
                off ^= (off >> 3) & 0x70;
                LDSM4(qhA[kk][0], qhA[kk][1], qhA[kk][2], qhA[kk][3], sb + FQH + off);
                LDSM4(qlA[kk][0], qlA[kk][1], qlA[kk][2], qlA[kk][3], sb + FQL + off);
            }
        }

        const uint32_t st  = sb + FST + (uint32_t)(kt & 1) * FSTAGE;
        const uint32_t sKh = st, sKl = st + 16384, sVh = st + 32768, sVl = st + 49152;

        // ---- S = Q K^T (128 keys) ----
        float sacc[16][4];
#pragma unroll
        for (int nf = 0; nf < 16; nf++)
#pragma unroll
            for (int r = 0; r < 4; r++) sacc[nf][r] = 0.f;

#pragma unroll
        for (int kk = 0; kk < 4; kk++) {
#pragma unroll
            for (int nfp = 0; nfp < 8; nfp++) {
                uint32_t off = (uint32_t)(nfp * 16 + brow) * 128 + kk * 32 + bcolb;
                off ^= (off >> 3) & 0x70;
                uint32_t bh0, bh1, bh2, bh3, bl0, bl1, bl2, bl3;
                LDSM4(bh0, bh1, bh2, bh3, sKh + off);
                LDSM4(bl0, bl1, bl2, bl3, sKl + off);
                MMA16816(sacc[nfp*2],   qhA[kk][0], qhA[kk][1], qhA[kk][2], qhA[kk][3], bh0, bh1);
                MMA16816(sacc[nfp*2],   qhA[kk][0], qhA[kk][1], qhA[kk][2], qhA[kk][3], bl0, bl1);
                MMA16816(sacc[nfp*2],   qlA[kk][0], qlA[kk][1], qlA[kk][2], qlA[kk][3], bh0, bh1);
                MMA16816(sacc[nfp*2+1], qhA[kk][0], qhA[kk][1], qhA[kk][2], qhA[kk][3], bh2, bh3);
                MMA16816(sacc[nfp*2+1], qhA[kk][0], qhA[kk][1], qhA[kk][2], qhA[kk][3], bl2, bl3);
                MMA16816(sacc[nfp*2+1], qlA[kk][0], qlA[kk][1], qlA[kk][2], qlA[kk][3], bh2, bh3);
            }
        }

        // ---- scale + causal mask + row max ----
        const float sc = 0.125f;
        const bool domask = (kt == nkt - 1);
        float mx0 = -1e30f, mx1 = -1e30f;
#pragma unroll
        for (int nf = 0; nf < 16; nf++) {
            int key = kt * 128 + nf * 8 + (lane & 3) * 2;
            float s0 = sacc[nf][0] * sc;
            float s1 = sacc[nf][1] * sc;
            float s2 = sacc[nf][2] * sc;
            float s3 = sacc[nf][3] * sc;
            if (domask) {
                if (key     > r0g) s0 = -1e30f;
                if (key + 1 > r0g) s1 = -1e30f;
                if (key     > r1g) s2 = -1e30f;
                if (key + 1 > r1g) s3 = -1e30f;
            }
            sacc[nf][0] = s0; sacc[nf][1] = s1; sacc[nf][2] = s2; sacc[nf][3] = s3;
            mx0 = fmaxf(mx0, fmaxf(s0, s1));
            mx1 = fmaxf(mx1, fmaxf(s2, s3));
        }
        mx0 = fmaxf(mx0, __shfl_xor_sync(0xffffffffu, mx0, 1));
        mx0 = fmaxf(mx0, __shfl_xor_sync(0xffffffffu, mx0, 2));
        mx1 = fmaxf(mx1, __shfl_xor_sync(0xffffffffu, mx1, 1));
        mx1 = fmaxf(mx1, __shfl_xor_sync(0xffffffffu, mx1, 2));

        float mn0 = fmaxf(m0, mx0), mn1 = fmaxf(m1, mx1);
        float al0 = __expf(m0 - mn0), al1 = __expf(m1 - mn1);

        // rescale accumulators
#pragma unroll
        for (int nf = 0; nf < 8; nf++) {
            out[nf][0] *= al0; out[nf][1] *= al0;
            out[nf][2] *= al1; out[nf][3] *= al1;
        }

        // ---- exp + P fragments + P.V (interleaved per kk) ----
        float sum0 = 0.f, sum1 = 0.f;
#pragma unroll
        for (int kk = 0; kk < 8; kk++) {
            uint32_t ph[4], pl[4];
#pragma unroll
            for (int half = 0; half < 2; half++) {
                int nf = kk * 2 + half;
                float p0 = __expf(sacc[nf][0] - mn0);
                float p1 = __expf(sacc[nf][1] - mn0);
                float p2 = __expf(sacc[nf][2] - mn1);
                float p3 = __expf(sacc[nf][3] - mn1);
                sum0 += p0 + p1;
                sum1 += p2 + p3;
                __nv_bfloat16 h0 = __float2bfloat16(p0), h1 = __float2bfloat16(p1);
                __nv_bfloat16 h2 = __float2bfloat16(p2), h3 = __float2bfloat16(p3);
                float e0 = p0 - __bfloat162float(h0), e1 = p1 - __bfloat162float(h1);
                float e2 = p2 - __bfloat162float(h2), e3 = p3 - __bfloat162float(h3);
                __nv_bfloat162 ph01 = __halves2bfloat162(h0, h1);
                __nv_bfloat162 ph23 = __halves2bfloat162(h2, h3);
                ph[half*2]     = *(uint32_t*)&ph01;
                ph[half*2 + 1] = *(uint32_t*)&ph23;
                pl[half*2]     = pack_bf16(e0, e1);
                pl[half*2 + 1] = pack_bf16(e2, e3);
            }
#pragma unroll
            for (int jp = 0; jp < 8; jp += 2) {
                uint32_t off = (uint32_t)(kk * 16 + vrow) * 128 + (jp + vcsel) * 16;
                off ^= (off >> 3) & 0x70;
                uint32_t vh0, vh1, vh2, vh3, vl0, vl1, vl2, vl3;
                LDSM4T(vh0, vh1, vh2, vh3, sVh + off);
                LDSM4T(vl0, vl1, vl2, vl3, sVl + off);
                MMA16816(out[jp],   ph[0], ph[1], ph[2], ph[3], vh0, vh1);
                MMA16816(out[jp],   ph[0], ph[1], ph[2], ph[3], vl0, vl1);
                MMA16816(out[jp],   pl[0], pl[1], pl[2], pl[3], vh0, vh1);
                MMA16816(out[jp+1], ph[0], ph[1], ph[2], ph[3], vh2, vh3);
                MMA16816(out[jp+1], ph[0], ph[1], ph[2], ph[3], vl2, vl3);
                MMA16816(out[jp+1], pl[0], pl[1], pl[2], pl[3], vh2, vh3);
            }
        }
        sum0 += __shfl_xor_sync(0xffffffffu, sum0, 1);
        sum0 += __shfl_xor_sync(0xffffffffu, sum0, 2);
        sum1 += __shfl_xor_sync(0xffffffffu, sum1, 1);
        sum1 += __shfl_xor_sync(0xffffffffu, sum1, 2);
        l0 = l0 * al0 + sum0;
        l1 = l1 * al1 + sum1;
        m0 = mn0; m1 = mn1;
    }

    // ---- epilogue ----
    float inv0 = 1.f / l0, inv1 = 1.f / l1;
#pragma unroll
    for (int nf = 0; nf < 8; nf++) {
        int col = h * HDIM + nf * 8 + (lane & 3) * 2;
        size_t i0 = (size_t)(b * SEQ + r0g) * DMODEL + col;
        size_t i1 = (size_t)(b * SEQ + r1g) * DMODEL + col;
        store_split2(Oh, Ol, i0, out[nf][0] * inv0, out[nf][1] * inv0);
        store_split2(Oh, Ol, i1, out[nf][2] * inv1, out[nf][3] * inv1);
    }
}

// ---------------- launcher ---------------------------------------------------
extern "C" void kernel_launch(void* const* d_in, const int* in_sizes, int n_in,
                              void* d_out, int out_size)
{
    const float* x  = (const float*)d_in[0];
    const float* Wq = (const float*)d_in[2];
    const float* Wk = (const float*)d_in[3];
    const float* Wv = (const float*)d_in[4];
    const float* Wo = (const float*)d_in[5];
    float* out = (float*)d_out;

    float *kfb, *vfb;
    cudaGetSymbolAddress((void**)&kfb, g_kfb);
    cudaGetSymbolAddress((void**)&vfb, g_vfb);

    __nv_bfloat16 *xh, *xl, *wqh, *wql, *wkh, *wkl, *wvh, *wvl, *woh, *wol;
    __nv_bfloat16 *qh, *ql, *kh, *kl, *vh, *vl;
    cudaGetSymbolAddress((void**)&xh, g_xh);
    cudaGetSymbolAddress((void**)&xl, g_xl);
    cudaGetSymbolAddress((void**)&wqh, g_wqh);
    cudaGetSymbolAddress((void**)&wql, g_wql);
    cudaGetSymbolAddress((void**)&wkh, g_wkh);
    cudaGetSymbolAddress((void**)&wkl, g_wkl);
    cudaGetSymbolAddress((void**)&wvh, g_wvh);
    cudaGetSymbolAddress((void**)&wvl, g_wvl);
    cudaGetSymbolAddress((void**)&woh, g_woh);
    cudaGetSymbolAddress((void**)&wol, g_wol);
    cudaGetSymbolAddress((void**)&qh, g_qh);
    cudaGetSymbolAddress((void**)&ql, g_ql);
    cudaGetSymbolAddress((void**)&kh, g_kh);
    cudaGetSymbolAddress((void**)&kl, g_kl);
    cudaGetSymbolAddress((void**)&vh, g_vh);
    cudaGetSymbolAddress((void**)&vl, g_vl);

    float* kdst;
    float* vdst;
    if (out_size >= OUTN + 2 * KVN) {
        kdst = out + OUTN;
        vdst = out + OUTN + KVN;
    } else {
        kdst = kfb;
        vdst = vfb;
    }

    cudaFuncSetAttribute(mma_gemm, cudaFuncAttributeMaxDynamicSharedMemorySize, GEMM_SMEM);
    cudaFuncSetAttribute(qkv_gemm, cudaFuncAttributeMaxDynamicSharedMemorySize, GEMM_SMEM);
    cudaFuncSetAttribute(flash_mma, cudaFuncAttributeMaxDynamicSharedMemorySize, FLASH_SMEM);

    RopeTab tab;
    for (int p = 0; p < 32; p++) {
        double invf = exp(-(double)p * (log(10000.0) / 32.0));
        float hi = (float)invf;
        tab.hi[p] = hi;
        tab.lo[p] = (float)(invf - (double)hi);
    }

    // splits: x + 4 weights
    split_kernel<<<OUTN/4/256, 256>>>((const float4*)x, (__nv_bfloat162*)xh, (__nv_bfloat162*)xl, OUTN/4);
    Ptrs4 wp;
    wp.s[0] = (const float4*)Wq; wp.h[0] = (__nv_bfloat162*)wqh; wp.l[0] = (__nv_bfloat162*)wql;
    wp.s[1] = (const float4*)Wk; wp.h[1] = (__nv_bfloat162*)wkh; wp.l[1] = (__nv_bfloat162*)wkl;
    wp.s[2] = (const float4*)Wv; wp.h[2] = (__nv_bfloat162*)wvh; wp.l[2] = (__nv_bfloat162*)wvl;
    wp.s[3] = (const float4*)Wo; wp.h[3] = (__nv_bfloat162*)woh; wp.l[3] = (__nv_bfloat162*)wol;
    dim3 wgrid(WN/4/256, 4);
    wsplit<<<wgrid, 256>>>(wp, WN/4);

    // fused QKV projection + RoPE + split (one launch, 768 CTAs)
    dim3 ggrid(DMODEL / 128, MROWS / 128, 3);   // (8, 32, 3)
    qkv_gemm<<<ggrid, 256, GEMM_SMEM>>>(xh, xl,
                                        wqh, wql, wkh, wkl, wvh, wvl,
                                        qh, ql, kh, kl, vh, vl,
                                        kdst, vdst, tab);

    // tensor-core flash attention -> split bf16 attn output (xh/xl reused)
    dim3 fgrid(SEQ / 128, NHEADS, BATCH);       // (16, 16, 2)
    flash_mma<<<fgrid, 256, FLASH_SMEM>>>(qh, ql, kh, kl, vh, vl, xh, xl);

    // output projection
    dim3 ogrid(DMODEL / 128, MROWS / 128);
    mma_gemm<<<ogrid, 256, GEMM_SMEM>>>(xh, xl, woh, wol, out);
}